// round 14
// baseline (speedup 1.0000x reference)
#include <cuda_runtime.h>
#include <cuda_bf16.h>
#include <cstdint>

// Problem constants
#define Bsz 2
#define Ssz 2048
#define Esz 1024
#define Hsz 16
#define HDd 64
#define Msz (Bsz * Ssz)      // 4096
#define NQKV (3 * Esz)       // 3072

// Q pre-scale: 1/sqrt(64) * log2(e)  (softmax runs in exp2 domain)
#define QSC 0.1803368801111244f

// bf16 hi/lo pre-split operands for the dense GEMMs
__device__ __nv_bfloat16 sXh[Msz * Esz], sXl[Msz * Esz];            // [m][k]
__device__ __nv_bfloat16 sWqh[NQKV * Esz], sWql[NQKV * Esz];        // [n][k]
__device__ __nv_bfloat16 sWph[Esz * Esz], sWpl[Esz * Esz];          // [n][k]
__device__ __nv_bfloat16 sOh[Msz * Esz], sOl[Msz * Esz];            // [m][k] merged heads

// bf16 hi/lo head-split Q/K/V: [B*H][S][64] (Q pre-scaled by QSC)
__device__ __nv_bfloat16 bQh[Bsz * Hsz * Ssz * HDd], bQl[Bsz * Hsz * Ssz * HDd];
__device__ __nv_bfloat16 bKh[Bsz * Hsz * Ssz * HDd], bKl[Bsz * Hsz * Ssz * HDd];
__device__ __nv_bfloat16 bVh[Bsz * Hsz * Ssz * HDd], bVl[Bsz * Hsz * Ssz * HDd];

// ---------------------------------------------------------------------------
// helpers
// ---------------------------------------------------------------------------
__device__ __forceinline__ void split2(float x0, float x1, uint32_t& hi, uint32_t& lo) {
    __nv_bfloat162 h = __floats2bfloat162_rn(x0, x1);
    float r0 = x0 - __bfloat162float(__low2bfloat16(h));
    float r1 = x1 - __bfloat162float(__high2bfloat16(h));
    __nv_bfloat162 l = __floats2bfloat162_rn(r0, r1);
    hi = *(uint32_t*)&h;
    lo = *(uint32_t*)&l;
}

__device__ __forceinline__ float ex2(float x) {
    float y;
    asm("ex2.approx.f32 %0, %1;" : "=f"(y) : "f"(x));
    return y;
}

__device__ __forceinline__ void mma16(float* d, const uint32_t* a, const uint32_t* b) {
    asm volatile(
        "mma.sync.aligned.m16n8k16.row.col.f32.bf16.bf16.f32 "
        "{%0,%1,%2,%3}, {%4,%5,%6,%7}, {%8,%9}, {%0,%1,%2,%3};"
        : "+f"(d[0]), "+f"(d[1]), "+f"(d[2]), "+f"(d[3])
        : "r"(a[0]), "r"(a[1]), "r"(a[2]), "r"(a[3]), "r"(b[0]), "r"(b[1]));
}

__device__ __forceinline__ void ldm4(uint32_t* r, uint32_t addr) {
    asm volatile("ldmatrix.sync.aligned.m8n8.x4.shared.b16 {%0,%1,%2,%3}, [%4];"
                 : "=r"(r[0]), "=r"(r[1]), "=r"(r[2]), "=r"(r[3]) : "r"(addr));
}

__device__ __forceinline__ void ldm4t(uint32_t* r, uint32_t addr) {
    asm volatile("ldmatrix.sync.aligned.m8n8.x4.trans.shared.b16 {%0,%1,%2,%3}, [%4];"
                 : "=r"(r[0]), "=r"(r[1]), "=r"(r[2]), "=r"(r[3]) : "r"(addr));
}

__device__ __forceinline__ void cp16(uint32_t dst, const void* src) {
    asm volatile("cp.async.cg.shared.global [%0], [%1], 16;"
                 :: "r"(dst), "l"(src));
}
#define CP_COMMIT() asm volatile("cp.async.commit_group;" ::: "memory")
#define CP_WAIT(n)  asm volatile("cp.async.wait_group %0;" :: "n"(n) : "memory")

__device__ __forceinline__ uint32_t smem_u32(const void* p) {
    uint32_t a;
    asm("{ .reg .u64 t; cvta.to.shared.u64 t, %1; cvt.u32.u64 %0, t; }"
        : "=r"(a) : "l"(p));
    return a;
}

// ---------------------------------------------------------------------------
// Dense GEMM machinery (proven): CTA 128x128, BK=32, 256 threads,
// pitch-80 smem, cp.async double buffer, ldmatrix, bf16x3.
// ---------------------------------------------------------------------------
#define TILE_B 10240            // 128 * 80
#define STAGE_B (4 * TILE_B)    // 40960
#define SMEM_DYN (2 * STAGE_B)  // 81920

__device__ __forceinline__ void load_stage(
    uint32_t sbst, const __nv_bfloat16* Ah, const __nv_bfloat16* Al,
    const __nv_bfloat16* Bh, const __nv_bfloat16* Bl,
    int m0, int n0, int k0, int tid) {
#pragma unroll
    for (int g = 0; g < 2; g++) {
        const int idx = g * 256 + tid;
        const int row = idx >> 2, ch = idx & 3;
        const uint32_t d = sbst + row * 80 + ch * 16;
        const int aoff = (m0 + row) * Esz + k0 + ch * 8;
        const int boff = (n0 + row) * Esz + k0 + ch * 8;
        cp16(d, Ah + aoff);
        cp16(d + TILE_B, Al + aoff);
        cp16(d + 2 * TILE_B, Bh + boff);
        cp16(d + 3 * TILE_B, Bl + boff);
    }
}

__device__ __forceinline__ void mma_stage(float acc[4][4][4], uint32_t sbst,
                                          int wm0, int wn0, int lane) {
    const int laneRowA = ((lane >> 3) & 1) * 8 + (lane & 7);
    const int chA = lane >> 4;
    const int laneRowB = (lane >> 4) * 8 + (lane & 7);
    const int chB = (lane >> 3) & 1;
#pragma unroll
    for (int ks = 0; ks < 2; ks++) {
        uint32_t ah[4][4], al[4][4], bh[2][4], bl[2][4];
#pragma unroll
        for (int i = 0; i < 4; i++) {
            const uint32_t ra =
                sbst + (wm0 + i * 16 + laneRowA) * 80 + (ks * 2 + chA) * 16;
            ldm4(ah[i], ra);
            ldm4(al[i], ra + TILE_B);
        }
#pragma unroll
        for (int jp = 0; jp < 2; jp++) {
            const uint32_t rb = sbst + 2 * TILE_B +
                (wn0 + jp * 16 + laneRowB) * 80 + (ks * 2 + chB) * 16;
            ldm4(bh[jp], rb);
            ldm4(bl[jp], rb + TILE_B);
        }
#pragma unroll
        for (int i = 0; i < 4; i++)
#pragma unroll
            for (int j = 0; j < 4; j++)
                mma16(acc[i][j], ah[i], &bh[j >> 1][(j & 1) * 2]);
#pragma unroll
        for (int i = 0; i < 4; i++)
#pragma unroll
            for (int j = 0; j < 4; j++)
                mma16(acc[i][j], ah[i], &bl[j >> 1][(j & 1) * 2]);
#pragma unroll
        for (int i = 0; i < 4; i++)
#pragma unroll
            for (int j = 0; j < 4; j++)
                mma16(acc[i][j], al[i], &bh[j >> 1][(j & 1) * 2]);
    }
}

#define GEMM_MAINLOOP(Ah, Al, Bh, Bl)                                        \
    extern __shared__ char dsm[];                                            \
    const uint32_t sb = smem_u32(dsm);                                       \
    const int tid = threadIdx.x;                                             \
    const int wid = tid >> 5, lane = tid & 31;                               \
    const int wm0 = (wid >> 2) * 64, wn0 = (wid & 3) * 32;                   \
    const int m0 = blockIdx.y * 128, n0 = blockIdx.x * 128;                  \
    float acc[4][4][4];                                                      \
    _Pragma("unroll") for (int i = 0; i < 4; i++)                            \
        _Pragma("unroll") for (int j = 0; j < 4; j++)                        \
            _Pragma("unroll") for (int r = 0; r < 4; r++) acc[i][j][r] = 0.f;\
    load_stage(sb, Ah, Al, Bh, Bl, m0, n0, 0, tid);                          \
    CP_COMMIT();                                                             \
    for (int s = 0; s < Esz / 32; s++) {                                     \
        CP_WAIT(0);                                                          \
        __syncthreads();                                                     \
        if (s + 1 < Esz / 32) {                                              \
            load_stage(sb + ((s + 1) & 1) * STAGE_B, Ah, Al, Bh, Bl,         \
                       m0, n0, (s + 1) * 32, tid);                           \
            CP_COMMIT();                                                     \
        }                                                                    \
        mma_stage(acc, sb + (s & 1) * STAGE_B, wm0, wn0, lane);              \
    }

// ---------------------------------------------------------------------------
// Kernel 1: qkv GEMM; epilogue writes pre-split bf16 Q/K/V (Q scaled QSC)
// ---------------------------------------------------------------------------
__global__ __launch_bounds__(256, 2) void gemm_qkv(const float* __restrict__ bias) {
    GEMM_MAINLOOP(sXh, sXl, sWqh, sWql)

    const int g2 = lane >> 2, t2 = lane & 3;
#pragma unroll
    for (int i = 0; i < 4; i++) {
#pragma unroll
        for (int j = 0; j < 4; j++) {
            const int r0 = m0 + wm0 + i * 16 + g2;
            const int c0 = n0 + wn0 + j * 8 + t2 * 2;
            const int part = c0 >> 10, e = c0 & 1023;
            const int hh = e >> 6, d = e & 63;
            __nv_bfloat16 *dh, *dl;
            if (part == 0)      { dh = bQh; dl = bQl; }
            else if (part == 1) { dh = bKh; dl = bKl; }
            else                { dh = bVh; dl = bVl; }
            const float sc = (part == 0) ? QSC : 1.f;
            const float bb0 = bias[c0], bb1 = bias[c0 + 1];
            {
                const int b = r0 >> 11, sq = r0 & 2047;
                const int off = (((b << 4) + hh) * Ssz + sq) * HDd + d;
                uint32_t hi, lo;
                split2((acc[i][j][0] + bb0) * sc, (acc[i][j][1] + bb1) * sc, hi, lo);
                *(uint32_t*)(dh + off) = hi;
                *(uint32_t*)(dl + off) = lo;
            }
            {
                const int r1 = r0 + 8;
                const int b = r1 >> 11, sq = r1 & 2047;
                const int off = (((b << 4) + hh) * Ssz + sq) * HDd + d;
                uint32_t hi, lo;
                split2((acc[i][j][2] + bb0) * sc, (acc[i][j][3] + bb1) * sc, hi, lo);
                *(uint32_t*)(dh + off) = hi;
                *(uint32_t*)(dl + off) = lo;
            }
        }
    }
}

// ---------------------------------------------------------------------------
// Kernel 3: proj GEMM -> d_out
// ---------------------------------------------------------------------------
__global__ __launch_bounds__(256, 2) void gemm_proj(const float* __restrict__ bias,
                                                    float* __restrict__ out) {
    GEMM_MAINLOOP(sOh, sOl, sWph, sWpl)

    const int g2 = lane >> 2, t2 = lane & 3;
#pragma unroll
    for (int i = 0; i < 4; i++) {
#pragma unroll
        for (int j = 0; j < 4; j++) {
            const int r0 = m0 + wm0 + i * 16 + g2;
            const int c0 = n0 + wn0 + j * 8 + t2 * 2;
            const float b0 = bias[c0], b1 = bias[c0 + 1];
            float2 v0 = make_float2(acc[i][j][0] + b0, acc[i][j][1] + b1);
            float2 v1 = make_float2(acc[i][j][2] + b0, acc[i][j][3] + b1);
            *(float2*)(out + r0 * Esz + c0) = v0;
            *(float2*)(out + (r0 + 8) * Esz + c0) = v1;
        }
    }
}

// ---------------------------------------------------------------------------
// Pre-split kernels: X (plain) and both weights (merged transpose kernel)
// ---------------------------------------------------------------------------
__global__ __launch_bounds__(256) void split_plain(const float4* __restrict__ src) {
    const int i = blockIdx.x * 256 + threadIdx.x;
    const float4 v = src[i];
    uint32_t h0, l0, h1, l1;
    split2(v.x, v.y, h0, l0);
    split2(v.z, v.w, h1, l1);
    ((uint2*)sXh)[i] = make_uint2(h0, h1);
    ((uint2*)sXl)[i] = make_uint2(l0, l1);
}

// grid.x: [0,96) -> w_qkv (N=3072), [96,128) -> w_proj (N=1024); grid.y = 32 k-blocks
__global__ __launch_bounds__(256) void split_w_all(const float* __restrict__ Wq,
                                                   const float* __restrict__ Wp) {
    __shared__ float tbuf[32][33];
    const float* W;
    __nv_bfloat16 *Th, *Tl;
    int N, nblk;
    if (blockIdx.x < 96) { W = Wq; Th = sWqh; Tl = sWql; N = NQKV; nblk = blockIdx.x; }
    else                 { W = Wp; Th = sWph; Tl = sWpl; N = Esz;  nblk = blockIdx.x - 96; }
    const int k0 = blockIdx.y * 32, n0 = nblk * 32;
    const int tx = threadIdx.x & 31, ty = threadIdx.x >> 5;
#pragma unroll
    for (int r = ty; r < 32; r += 8)
        tbuf[r][tx] = W[(k0 + r) * N + n0 + tx];
    __syncthreads();
#pragma unroll
    for (int r = ty; r < 32; r += 8) {
        const float v = tbuf[tx][r];
        __nv_bfloat16 h = __float2bfloat16_rn(v);
        __nv_bfloat16 l = __float2bfloat16_rn(v - __bfloat162float(h));
        Th[(n0 + r) * Esz + k0 + tx] = h;
        Tl[(n0 + r) * Esz + k0 + tx] = l;
    }
}

// ---------------------------------------------------------------------------
// Kernel 2: tensor-core causal flash attention, SPLIT-KV warps, 256 threads.
// grid = (32 q-tiles, 32 bh), 8 warps: warp = (mw 0..3, kw 0..1).
// mw owns q rows mw*16..+16 (ONE m16 frag), kw owns kv cols kw*32..+32.
// Each kw-warp keeps independent online softmax over its kv half; halves
// merge once at the end via smem in the dead Q region. K/V ldmatrix traffic
// halved AND per-thread registers halved vs round-13 (-> 2 CTAs/SM).
// ---------------------------------------------------------------------------
#define AT_PITCH 144
#define AT_TILE (64 * AT_PITCH)              // 9216
#define AT_STAGE0 (2 * AT_TILE)              // Q hi/lo region (dead after tt=0)
#define AT_STAGE_B (4 * AT_TILE)             // 36864
#define AT_SMEM (AT_STAGE0 + 2 * AT_STAGE_B) // 92160
#define OBP 68                               // O-combine row pitch (floats)

__device__ __forceinline__ void at_load_kv(uint32_t st, int base, int kv0, int tid) {
#pragma unroll
    for (int gq = 0; gq < 2; gq++) {
        const int idx = gq * 256 + tid;          // 0..511
        const int row = idx >> 3, ch = idx & 7;
        const uint32_t d = st + row * AT_PITCH + ch * 16;
        const int off = base + (kv0 + row) * HDd + ch * 8;
        cp16(d, bKh + off);
        cp16(d + AT_TILE, bKl + off);
        cp16(d + 2 * AT_TILE, bVh + off);
        cp16(d + 3 * AT_TILE, bVl + off);
    }
}

__global__ __launch_bounds__(256, 2) void attn_tc() {
    extern __shared__ char dsm[];
    const uint32_t sb = smem_u32(dsm);
    const int tid = threadIdx.x, wid = tid >> 5, lane = tid & 31;
    const int mw = wid >> 1;            // q-row quarter (0..3)
    const int kw = wid & 1;             // kv half
    const int bh = blockIdx.y;
    const int q0 = (gridDim.x - 1 - blockIdx.x) * 64;  // heavy tiles first
    const int wq0 = mw * 16;
    const int g = lane >> 2, t = lane & 3;
    const int base = bh * Ssz * HDd;

    // async: Q tile hi/lo (64 rows)
#pragma unroll
    for (int gq = 0; gq < 2; gq++) {
        const int idx = gq * 256 + tid;
        const int row = idx >> 3, ch = idx & 7;
        const uint32_t d = sb + row * AT_PITCH + ch * 16;
        const int off = base + (q0 + row) * HDd + ch * 8;
        cp16(d, bQh + off);
        cp16(d + AT_TILE, bQl + off);
    }
    at_load_kv(sb + AT_STAGE0, base, 0, tid);
    CP_COMMIT();

    const int T = q0 / 64 + 1;

    float oacc[8][4];
#pragma unroll
    for (int j = 0; j < 8; j++)
#pragma unroll
        for (int r = 0; r < 4; r++) oacc[j][r] = 0.f;
    float m_a = -1e30f, m_b = -1e30f, l_a = 0.f, l_b = 0.f;
    uint32_t qh[4][4], ql[4][4];

    const int laneRowB = (lane >> 4) * 8 + (lane & 7);
    const int chB = (lane >> 3) & 1;

    for (int tt = 0; tt < T; tt++) {
        if (tt + 1 < T) {
            at_load_kv(sb + AT_STAGE0 + ((tt + 1) & 1) * AT_STAGE_B,
                       base, (tt + 1) * 64, tid);
            CP_COMMIT();
            CP_WAIT(1);
        } else {
            CP_WAIT(0);
        }
        __syncthreads();

        if (tt == 0) {
#pragma unroll
            for (int ks = 0; ks < 4; ks++) {
                const uint32_t ra = sb + (wq0 + (lane & 15)) * AT_PITCH +
                                    (ks * 2 + (lane >> 4)) * 16;
                ldm4(qh[ks], ra);
                ldm4(ql[ks], ra + AT_TILE);
            }
        }

        const uint32_t st = sb + AT_STAGE0 + (tt & 1) * AT_STAGE_B;

        // S = Q K^T over own kv half (32 cols)
        float sacc[4][4];
#pragma unroll
        for (int j = 0; j < 4; j++)
#pragma unroll
            for (int r = 0; r < 4; r++) sacc[j][r] = 0.f;

#pragma unroll
        for (int ks = 0; ks < 4; ks++) {
#pragma unroll
            for (int jp = 0; jp < 2; jp++) {
                const uint32_t rb = st +
                    (kw * 32 + jp * 16 + laneRowB) * AT_PITCH +
                    (ks * 2 + chB) * 16;
                uint32_t kh4[4], kl4[4];
                ldm4(kh4, rb);
                ldm4(kl4, rb + AT_TILE);
                mma16(sacc[jp * 2],     qh[ks], &kh4[0]);
                mma16(sacc[jp * 2 + 1], qh[ks], &kh4[2]);
                mma16(sacc[jp * 2],     qh[ks], &kl4[0]);
                mma16(sacc[jp * 2 + 1], qh[ks], &kl4[2]);
                mma16(sacc[jp * 2],     ql[ks], &kh4[0]);
                mma16(sacc[jp * 2 + 1], ql[ks], &kh4[2]);
            }
        }

        // causal mask (diagonal tile only)
        const int rowa = q0 + wq0 + g;
        const int rowb = rowa + 8;
        if (tt == T - 1) {
            const int kvb = tt * 64;
#pragma unroll
            for (int j = 0; j < 4; j++) {
                const int c0 = kvb + kw * 32 + j * 8 + t * 2;
                if (c0 > rowa) sacc[j][0] = -1e30f;
                if (c0 + 1 > rowa) sacc[j][1] = -1e30f;
                if (c0 > rowb) sacc[j][2] = -1e30f;
                if (c0 + 1 > rowb) sacc[j][3] = -1e30f;
            }
        }

        // online softmax (own kv half only; exp2 domain)
        float mxa = -1e30f, mxb = -1e30f;
#pragma unroll
        for (int j = 0; j < 4; j++) {
            mxa = fmaxf(mxa, fmaxf(sacc[j][0], sacc[j][1]));
            mxb = fmaxf(mxb, fmaxf(sacc[j][2], sacc[j][3]));
        }
        mxa = fmaxf(mxa, __shfl_xor_sync(0xffffffffu, mxa, 1));
        mxa = fmaxf(mxa, __shfl_xor_sync(0xffffffffu, mxa, 2));
        mxb = fmaxf(mxb, __shfl_xor_sync(0xffffffffu, mxb, 1));
        mxb = fmaxf(mxb, __shfl_xor_sync(0xffffffffu, mxb, 2));
        const float mna = fmaxf(m_a, mxa), mnb = fmaxf(m_b, mxb);
        const float ca = ex2(m_a - mna), cb = ex2(m_b - mnb);
        m_a = mna;
        m_b = mnb;

        float ra = 0.f, rb = 0.f;
        uint32_t ph[2][4], pl[2][4];
#pragma unroll
        for (int j = 0; j < 4; j++) {
            const float p0 = ex2(sacc[j][0] - mna);
            const float p1 = ex2(sacc[j][1] - mna);
            const float p2 = ex2(sacc[j][2] - mnb);
            const float p3 = ex2(sacc[j][3] - mnb);
            ra += p0 + p1;
            rb += p2 + p3;
            uint32_t h01, l01, h23, l23;
            split2(p0, p1, h01, l01);
            split2(p2, p3, h23, l23);
            const int kc = j >> 1, half = (j & 1) * 2;
            ph[kc][half] = h01;
            ph[kc][half + 1] = h23;
            pl[kc][half] = l01;
            pl[kc][half + 1] = l23;
        }
        ra += __shfl_xor_sync(0xffffffffu, ra, 1);
        ra += __shfl_xor_sync(0xffffffffu, ra, 2);
        rb += __shfl_xor_sync(0xffffffffu, rb, 1);
        rb += __shfl_xor_sync(0xffffffffu, rb, 2);
        l_a = l_a * ca + ra;
        l_b = l_b * cb + rb;

#pragma unroll
        for (int j = 0; j < 8; j++) {
            oacc[j][0] *= ca;
            oacc[j][1] *= ca;
            oacc[j][2] *= cb;
            oacc[j][3] *= cb;
        }

        // O += P V over own kv half (32 rows of V)
        const uint32_t vbase = st + 2 * AT_TILE;
#pragma unroll
        for (int kc = 0; kc < 2; kc++) {
#pragma unroll
            for (int jp = 0; jp < 4; jp++) {
                const uint32_t va = vbase +
                    (kw * 32 + kc * 16 + (lane & 15)) * AT_PITCH +
                    (jp * 16 + (lane >> 4) * 8) * 2;
                uint32_t vh4[4], vl4[4];
                ldm4t(vh4, va);
                ldm4t(vl4, va + AT_TILE);
                mma16(oacc[jp * 2],     ph[kc], &vh4[0]);
                mma16(oacc[jp * 2 + 1], ph[kc], &vh4[2]);
                mma16(oacc[jp * 2],     ph[kc], &vl4[0]);
                mma16(oacc[jp * 2 + 1], ph[kc], &vl4[2]);
                mma16(oacc[jp * 2],     pl[kc], &vh4[0]);
                mma16(oacc[jp * 2 + 1], pl[kc], &vh4[2]);
            }
        }
        __syncthreads();
    }

    // -------- split-KV combine (once per CTA) via dead Q smem region --------
    float* exm = (float*)dsm;            // [2 kw][64 rows]
    float* exl = exm + 128;
    float* ob  = exl + 128;              // [64 rows][OBP]

    if (t == 0) {
        const int r0 = wq0 + g;
        exm[kw * 64 + r0] = m_a;
        exl[kw * 64 + r0] = l_a;
        exm[kw * 64 + r0 + 8] = m_b;
        exl[kw * 64 + r0 + 8] = l_b;
    }
    __syncthreads();

    float sc_[2], linv[2];
    {
        const int r0 = wq0 + g;
        const float mo[2] = {m_a, m_b};
        const float lo_[2] = {l_a, l_b};
#pragma unroll
        for (int ab = 0; ab < 2; ab++) {
            const int r = r0 + ab * 8;
            const float mp = exm[(kw ^ 1) * 64 + r];
            const float lp = exl[(kw ^ 1) * 64 + r];
            const float mj = fmaxf(mo[ab], mp);
            const float so = ex2(mo[ab] - mj), sp = ex2(mp - mj);
            sc_[ab] = so;
            linv[ab] = 1.f / (lo_[ab] * so + lp * sp);
        }
    }

    if (kw == 0) {
#pragma unroll
        for (int j = 0; j < 8; j++) {
            const int r0 = wq0 + g, r1 = r0 + 8;
            const int col = j * 8 + t * 2;
            ob[r0 * OBP + col]     = oacc[j][0] * sc_[0];
            ob[r0 * OBP + col + 1] = oacc[j][1] * sc_[0];
            ob[r1 * OBP + col]     = oacc[j][2] * sc_[1];
            ob[r1 * OBP + col + 1] = oacc[j][3] * sc_[1];
        }
    }
    __syncthreads();
    if (kw == 1) {
#pragma unroll
        for (int j = 0; j < 8; j++) {
            const int r0 = wq0 + g, r1 = r0 + 8;
            const int col = j * 8 + t * 2;
            ob[r0 * OBP + col]     += oacc[j][0] * sc_[0];
            ob[r0 * OBP + col + 1] += oacc[j][1] * sc_[0];
            ob[r1 * OBP + col]     += oacc[j][2] * sc_[1];
            ob[r1 * OBP + col + 1] += oacc[j][3] * sc_[1];
        }
    }
    __syncthreads();

    // write merged-head pre-split output; each warp writes its kw half of cols
    const int b = bh >> 4, h = bh & 15;
#pragma unroll
    for (int ab = 0; ab < 2; ab++) {
        const int r = wq0 + g + ab * 8;
        const float li = linv[ab];
        const int mo = (b * Ssz + q0 + r) * Esz + h * HDd;
#pragma unroll
        for (int j2 = 0; j2 < 4; j2++) {
            const int col = kw * 32 + j2 * 8 + t * 2;
            const float v0 = ob[r * OBP + col] * li;
            const float v1 = ob[r * OBP + col + 1] * li;
            uint32_t hi, lo;
            split2(v0, v1, hi, lo);
            *(uint32_t*)(sOh + mo + col) = hi;
            *(uint32_t*)(sOl + mo + col) = lo;
        }
    }
}

// ---------------------------------------------------------------------------
extern "C" void kernel_launch(void* const* d_in, const int* in_sizes, int n_in,
                              void* d_out, int out_size) {
    const float* x = (const float*)d_in[0];
    const float* w_qkv = (const float*)d_in[1];
    const float* b_qkv = (const float*)d_in[2];
    const float* w_proj = (const float*)d_in[3];
    const float* b_proj = (const float*)d_in[4];
    float* out = (float*)d_out;

    static bool attr_done = false;
    if (!attr_done) {
        cudaFuncSetAttribute(gemm_qkv, cudaFuncAttributeMaxDynamicSharedMemorySize, SMEM_DYN);
        cudaFuncSetAttribute(gemm_proj, cudaFuncAttributeMaxDynamicSharedMemorySize, SMEM_DYN);
        cudaFuncSetAttribute(attn_tc, cudaFuncAttributeMaxDynamicSharedMemorySize, AT_SMEM);
        attr_done = true;
    }

    split_plain<<<Msz * Esz / 4 / 256, 256>>>((const float4*)x);
    split_w_all<<<dim3(128, 32), 256>>>(w_qkv, w_proj);
    gemm_qkv<<<dim3(NQKV / 128, Msz / 128), 256, SMEM_DYN>>>(b_qkv);
    attn_tc<<<dim3(Ssz / 64, Bsz * Hsz), 256, AT_SMEM>>>();
    gemm_proj<<<dim3(Esz / 128, Msz / 128), 256, SMEM_DYN>>>(b_proj, out);
}

// round 15
// speedup vs baseline: 1.0159x; 1.0159x over previous
#include <cuda_runtime.h>
#include <cuda_bf16.h>
#include <cstdint>

// Problem constants
#define Bsz 2
#define Ssz 2048
#define Esz 1024
#define Hsz 16
#define HDd 64
#define Msz (Bsz * Ssz)      // 4096
#define NQKV (3 * Esz)       // 3072

// Q pre-scale: 1/sqrt(64) * log2(e)  (softmax runs in exp2 domain)
#define QSC 0.1803368801111244f

// bf16 hi/lo pre-split operands for the dense GEMMs
__device__ __nv_bfloat16 sXh[Msz * Esz], sXl[Msz * Esz];            // [m][k]
__device__ __nv_bfloat16 sWqh[NQKV * Esz], sWql[NQKV * Esz];        // [n][k]
__device__ __nv_bfloat16 sWph[Esz * Esz], sWpl[Esz * Esz];          // [n][k]
__device__ __nv_bfloat16 sOh[Msz * Esz], sOl[Msz * Esz];            // [m][k] merged heads

// bf16 hi/lo head-split Q/K/V: [B*H][S][64] (Q pre-scaled by QSC)
__device__ __nv_bfloat16 bQh[Bsz * Hsz * Ssz * HDd], bQl[Bsz * Hsz * Ssz * HDd];
__device__ __nv_bfloat16 bKh[Bsz * Hsz * Ssz * HDd], bKl[Bsz * Hsz * Ssz * HDd];
__device__ __nv_bfloat16 bVh[Bsz * Hsz * Ssz * HDd], bVl[Bsz * Hsz * Ssz * HDd];

// ---------------------------------------------------------------------------
// helpers
// ---------------------------------------------------------------------------
__device__ __forceinline__ void split2(float x0, float x1, uint32_t& hi, uint32_t& lo) {
    __nv_bfloat162 h = __floats2bfloat162_rn(x0, x1);
    float r0 = x0 - __bfloat162float(__low2bfloat16(h));
    float r1 = x1 - __bfloat162float(__high2bfloat16(h));
    __nv_bfloat162 l = __floats2bfloat162_rn(r0, r1);
    hi = *(uint32_t*)&h;
    lo = *(uint32_t*)&l;
}

__device__ __forceinline__ float ex2(float x) {
    float y;
    asm("ex2.approx.f32 %0, %1;" : "=f"(y) : "f"(x));
    return y;
}

__device__ __forceinline__ void mma16(float* d, const uint32_t* a, const uint32_t* b) {
    asm volatile(
        "mma.sync.aligned.m16n8k16.row.col.f32.bf16.bf16.f32 "
        "{%0,%1,%2,%3}, {%4,%5,%6,%7}, {%8,%9}, {%0,%1,%2,%3};"
        : "+f"(d[0]), "+f"(d[1]), "+f"(d[2]), "+f"(d[3])
        : "r"(a[0]), "r"(a[1]), "r"(a[2]), "r"(a[3]), "r"(b[0]), "r"(b[1]));
}

__device__ __forceinline__ void ldm4(uint32_t* r, uint32_t addr) {
    asm volatile("ldmatrix.sync.aligned.m8n8.x4.shared.b16 {%0,%1,%2,%3}, [%4];"
                 : "=r"(r[0]), "=r"(r[1]), "=r"(r[2]), "=r"(r[3]) : "r"(addr));
}

__device__ __forceinline__ void ldm4t(uint32_t* r, uint32_t addr) {
    asm volatile("ldmatrix.sync.aligned.m8n8.x4.trans.shared.b16 {%0,%1,%2,%3}, [%4];"
                 : "=r"(r[0]), "=r"(r[1]), "=r"(r[2]), "=r"(r[3]) : "r"(addr));
}

__device__ __forceinline__ void cp16(uint32_t dst, const void* src) {
    asm volatile("cp.async.cg.shared.global [%0], [%1], 16;"
                 :: "r"(dst), "l"(src));
}
#define CP_COMMIT() asm volatile("cp.async.commit_group;" ::: "memory")
#define CP_WAIT(n)  asm volatile("cp.async.wait_group %0;" :: "n"(n) : "memory")

__device__ __forceinline__ uint32_t smem_u32(const void* p) {
    uint32_t a;
    asm("{ .reg .u64 t; cvta.to.shared.u64 t, %1; cvt.u32.u64 %0, t; }"
        : "=r"(a) : "l"(p));
    return a;
}

// ---------------------------------------------------------------------------
// Dense GEMM machinery: CTA 128x128, BK=32, 256 threads, pitch-80 smem,
// cp.async double buffer, ldmatrix, bf16x3. Global-load addresses are
// loop-carried byte pointers (+64B/stage); second half via constant offsets.
// ---------------------------------------------------------------------------
#define TILE_B 10240            // 128 * 80
#define STAGE_B (4 * TILE_B)    // 40960
#define SMEM_DYN (2 * STAGE_B)  // 81920
#define GOFF 131072             // 64 rows * 1024 k * 2 B
#define SOFF 5120               // 64 rows * 80 B

#define LOAD_ONE(base)                                                \
    do {                                                              \
        cp16((base) + dsoff, pA);                                     \
        cp16((base) + dsoff + TILE_B, pAl);                           \
        cp16((base) + dsoff + 2 * TILE_B, pB);                        \
        cp16((base) + dsoff + 3 * TILE_B, pBl);                       \
        cp16((base) + dsoff + SOFF, pA + GOFF);                       \
        cp16((base) + dsoff + SOFF + TILE_B, pAl + GOFF);             \
        cp16((base) + dsoff + SOFF + 2 * TILE_B, pB + GOFF);          \
        cp16((base) + dsoff + SOFF + 3 * TILE_B, pBl + GOFF);         \
    } while (0)

__device__ __forceinline__ void mma_stage(float acc[4][4][4], uint32_t sbst,
                                          int wm0, int wn0, int lane) {
    const int laneRowA = ((lane >> 3) & 1) * 8 + (lane & 7);
    const int chA = lane >> 4;
    const int laneRowB = (lane >> 4) * 8 + (lane & 7);
    const int chB = (lane >> 3) & 1;
#pragma unroll
    for (int ks = 0; ks < 2; ks++) {
        uint32_t ah[4][4], al[4][4], bh[2][4], bl[2][4];
#pragma unroll
        for (int i = 0; i < 4; i++) {
            const uint32_t ra =
                sbst + (wm0 + i * 16 + laneRowA) * 80 + (ks * 2 + chA) * 16;
            ldm4(ah[i], ra);
            ldm4(al[i], ra + TILE_B);
        }
#pragma unroll
        for (int jp = 0; jp < 2; jp++) {
            const uint32_t rb = sbst + 2 * TILE_B +
                (wn0 + jp * 16 + laneRowB) * 80 + (ks * 2 + chB) * 16;
            ldm4(bh[jp], rb);
            ldm4(bl[jp], rb + TILE_B);
        }
#pragma unroll
        for (int i = 0; i < 4; i++)
#pragma unroll
            for (int j = 0; j < 4; j++)
                mma16(acc[i][j], ah[i], &bh[j >> 1][(j & 1) * 2]);
#pragma unroll
        for (int i = 0; i < 4; i++)
#pragma unroll
            for (int j = 0; j < 4; j++)
                mma16(acc[i][j], ah[i], &bl[j >> 1][(j & 1) * 2]);
#pragma unroll
        for (int i = 0; i < 4; i++)
#pragma unroll
            for (int j = 0; j < 4; j++)
                mma16(acc[i][j], al[i], &bh[j >> 1][(j & 1) * 2]);
    }
}

#define GEMM_MAINLOOP(Ah, Al, Bh, Bl)                                        \
    extern __shared__ char dsm[];                                            \
    const uint32_t sb = smem_u32(dsm);                                       \
    const int tid = threadIdx.x;                                             \
    const int wid = tid >> 5, lane = tid & 31;                               \
    const int wm0 = (wid >> 2) * 64, wn0 = (wid & 3) * 32;                   \
    const int m0 = blockIdx.y * 128, n0 = blockIdx.x * 128;                  \
    const int ldrow = tid >> 2, ldch = tid & 3;                              \
    const uint32_t dsoff = (uint32_t)(ldrow * 80 + ldch * 16);               \
    const char* pA  = (const char*)((Ah) + (m0 + ldrow) * Esz + ldch * 8);   \
    const char* pAl = (const char*)((Al) + (m0 + ldrow) * Esz + ldch * 8);   \
    const char* pB  = (const char*)((Bh) + (n0 + ldrow) * Esz + ldch * 8);   \
    const char* pBl = (const char*)((Bl) + (n0 + ldrow) * Esz + ldch * 8);   \
    float acc[4][4][4];                                                      \
    _Pragma("unroll") for (int i = 0; i < 4; i++)                            \
        _Pragma("unroll") for (int j = 0; j < 4; j++)                        \
            _Pragma("unroll") for (int r = 0; r < 4; r++) acc[i][j][r] = 0.f;\
    LOAD_ONE(sb);                                                            \
    CP_COMMIT();                                                             \
    pA += 64; pAl += 64; pB += 64; pBl += 64;                                \
    for (int s = 0; s < Esz / 32; s++) {                                     \
        CP_WAIT(0);                                                          \
        __syncthreads();                                                     \
        if (s + 1 < Esz / 32) {                                              \
            LOAD_ONE(sb + ((s + 1) & 1) * STAGE_B);                          \
            CP_COMMIT();                                                     \
            pA += 64; pAl += 64; pB += 64; pBl += 64;                        \
        }                                                                    \
        mma_stage(acc, sb + (s & 1) * STAGE_B, wm0, wn0, lane);              \
    }

// ---------------------------------------------------------------------------
// Kernel 1: qkv GEMM; epilogue writes pre-split bf16 Q/K/V (Q scaled QSC)
// ---------------------------------------------------------------------------
__global__ __launch_bounds__(256, 2) void gemm_qkv(const float* __restrict__ bias) {
    GEMM_MAINLOOP(sXh, sXl, sWqh, sWql)

    const int g2 = lane >> 2, t2 = lane & 3;
#pragma unroll
    for (int i = 0; i < 4; i++) {
#pragma unroll
        for (int j = 0; j < 4; j++) {
            const int r0 = m0 + wm0 + i * 16 + g2;
            const int c0 = n0 + wn0 + j * 8 + t2 * 2;
            const int part = c0 >> 10, e = c0 & 1023;
            const int hh = e >> 6, d = e & 63;
            __nv_bfloat16 *dh, *dl;
            if (part == 0)      { dh = bQh; dl = bQl; }
            else if (part == 1) { dh = bKh; dl = bKl; }
            else                { dh = bVh; dl = bVl; }
            const float sc = (part == 0) ? QSC : 1.f;
            const float bb0 = bias[c0], bb1 = bias[c0 + 1];
            {
                const int b = r0 >> 11, sq = r0 & 2047;
                const int off = (((b << 4) + hh) * Ssz + sq) * HDd + d;
                uint32_t hi, lo;
                split2((acc[i][j][0] + bb0) * sc, (acc[i][j][1] + bb1) * sc, hi, lo);
                *(uint32_t*)(dh + off) = hi;
                *(uint32_t*)(dl + off) = lo;
            }
            {
                const int r1 = r0 + 8;
                const int b = r1 >> 11, sq = r1 & 2047;
                const int off = (((b << 4) + hh) * Ssz + sq) * HDd + d;
                uint32_t hi, lo;
                split2((acc[i][j][2] + bb0) * sc, (acc[i][j][3] + bb1) * sc, hi, lo);
                *(uint32_t*)(dh + off) = hi;
                *(uint32_t*)(dl + off) = lo;
            }
        }
    }
}

// ---------------------------------------------------------------------------
// Kernel 3: proj GEMM -> d_out
// ---------------------------------------------------------------------------
__global__ __launch_bounds__(256, 2) void gemm_proj(const float* __restrict__ bias,
                                                    float* __restrict__ out) {
    GEMM_MAINLOOP(sOh, sOl, sWph, sWpl)

    const int g2 = lane >> 2, t2 = lane & 3;
#pragma unroll
    for (int i = 0; i < 4; i++) {
#pragma unroll
        for (int j = 0; j < 4; j++) {
            const int r0 = m0 + wm0 + i * 16 + g2;
            const int c0 = n0 + wn0 + j * 8 + t2 * 2;
            const float b0 = bias[c0], b1 = bias[c0 + 1];
            float2 v0 = make_float2(acc[i][j][0] + b0, acc[i][j][1] + b1);
            float2 v1 = make_float2(acc[i][j][2] + b0, acc[i][j][3] + b1);
            *(float2*)(out + r0 * Esz + c0) = v0;
            *(float2*)(out + (r0 + 8) * Esz + c0) = v1;
        }
    }
}

// ---------------------------------------------------------------------------
// Pre-split kernels: X (plain) and both weights (merged transpose kernel)
// ---------------------------------------------------------------------------
__global__ __launch_bounds__(256) void split_plain(const float4* __restrict__ src) {
    const int i = blockIdx.x * 256 + threadIdx.x;
    const float4 v = src[i];
    uint32_t h0, l0, h1, l1;
    split2(v.x, v.y, h0, l0);
    split2(v.z, v.w, h1, l1);
    ((uint2*)sXh)[i] = make_uint2(h0, h1);
    ((uint2*)sXl)[i] = make_uint2(l0, l1);
}

__global__ __launch_bounds__(256) void split_w_all(const float* __restrict__ Wq,
                                                   const float* __restrict__ Wp) {
    __shared__ float tbuf[32][33];
    const float* W;
    __nv_bfloat16 *Th, *Tl;
    int N, nblk;
    if (blockIdx.x < 96) { W = Wq; Th = sWqh; Tl = sWql; N = NQKV; nblk = blockIdx.x; }
    else                 { W = Wp; Th = sWph; Tl = sWpl; N = Esz;  nblk = blockIdx.x - 96; }
    const int k0 = blockIdx.y * 32, n0 = nblk * 32;
    const int tx = threadIdx.x & 31, ty = threadIdx.x >> 5;
#pragma unroll
    for (int r = ty; r < 32; r += 8)
        tbuf[r][tx] = W[(k0 + r) * N + n0 + tx];
    __syncthreads();
#pragma unroll
    for (int r = ty; r < 32; r += 8) {
        const float v = tbuf[tx][r];
        __nv_bfloat16 h = __float2bfloat16_rn(v);
        __nv_bfloat16 l = __float2bfloat16_rn(v - __bfloat162float(h));
        Th[(n0 + r) * Esz + k0 + tx] = h;
        Tl[(n0 + r) * Esz + k0 + tx] = l;
    }
}

// ---------------------------------------------------------------------------
// Kernel 2: tensor-core causal flash attention, SPLIT-KV (round-13 geometry:
// 128 threads, warp (mw,kw), mw owns 32 q-rows, kw owns 32-kv-col half),
// plus warp-collective rescale skip when the running max didn't grow.
// ---------------------------------------------------------------------------
#define AT_PITCH 144
#define AT_TILE (64 * AT_PITCH)              // 9216
#define AT_STAGE0 (2 * AT_TILE)              // Q hi/lo region (dead after tt=0)
#define AT_STAGE_B (4 * AT_TILE)             // 36864
#define AT_SMEM (AT_STAGE0 + 2 * AT_STAGE_B) // 92160
#define OBP 68                               // O-combine row pitch (floats)

__device__ __forceinline__ void at_load_kv(uint32_t st, int base, int kv0, int tid) {
#pragma unroll
    for (int gq = 0; gq < 4; gq++) {
        const int idx = gq * 128 + tid;          // 0..511
        const int row = idx >> 3, ch = idx & 7;
        const uint32_t d = st + row * AT_PITCH + ch * 16;
        const int off = base + (kv0 + row) * HDd + ch * 8;
        cp16(d, bKh + off);
        cp16(d + AT_TILE, bKl + off);
        cp16(d + 2 * AT_TILE, bVh + off);
        cp16(d + 3 * AT_TILE, bVl + off);
    }
}

__global__ __launch_bounds__(128, 2) void attn_tc() {
    extern __shared__ char dsm[];
    const uint32_t sb = smem_u32(dsm);
    const int tid = threadIdx.x, wid = tid >> 5, lane = tid & 31;
    const int mw = wid >> 1;            // q-row half
    const int kw = wid & 1;             // kv half
    const int bh = blockIdx.y;
    const int q0 = (gridDim.x - 1 - blockIdx.x) * 64;  // heavy tiles first
    const int wq0 = mw * 32;
    const int g = lane >> 2, t = lane & 3;
    const int base = bh * Ssz * HDd;

    // async: Q tile hi/lo (64 rows)
#pragma unroll
    for (int gq = 0; gq < 4; gq++) {
        const int idx = gq * 128 + tid;
        const int row = idx >> 3, ch = idx & 7;
        const uint32_t d = sb + row * AT_PITCH + ch * 16;
        const int off = base + (q0 + row) * HDd + ch * 8;
        cp16(d, bQh + off);
        cp16(d + AT_TILE, bQl + off);
    }
    at_load_kv(sb + AT_STAGE0, base, 0, tid);
    CP_COMMIT();

    const int T = q0 / 64 + 1;

    float oacc[2][8][4];
#pragma unroll
    for (int mf = 0; mf < 2; mf++)
#pragma unroll
        for (int j = 0; j < 8; j++)
#pragma unroll
            for (int r = 0; r < 4; r++) oacc[mf][j][r] = 0.f;
    float m_[2][2] = {{-1e30f, -1e30f}, {-1e30f, -1e30f}};
    float l_[2][2] = {{0.f, 0.f}, {0.f, 0.f}};
    uint32_t qh[2][4][4], ql[2][4][4];

    const int laneRowB = (lane >> 4) * 8 + (lane & 7);
    const int chB = (lane >> 3) & 1;

    for (int tt = 0; tt < T; tt++) {
        if (tt + 1 < T) {
            at_load_kv(sb + AT_STAGE0 + ((tt + 1) & 1) * AT_STAGE_B,
                       base, (tt + 1) * 64, tid);
            CP_COMMIT();
            CP_WAIT(1);
        } else {
            CP_WAIT(0);
        }
        __syncthreads();

        if (tt == 0) {
#pragma unroll
            for (int mf = 0; mf < 2; mf++)
#pragma unroll
                for (int ks = 0; ks < 4; ks++) {
                    const uint32_t ra = sb +
                        (wq0 + mf * 16 + (lane & 15)) * AT_PITCH +
                        (ks * 2 + (lane >> 4)) * 16;
                    ldm4(qh[mf][ks], ra);
                    ldm4(ql[mf][ks], ra + AT_TILE);
                }
        }

        const uint32_t st = sb + AT_STAGE0 + (tt & 1) * AT_STAGE_B;

        // S = Q K^T over own kv half (32 cols)
        float sacc[2][4][4];
#pragma unroll
        for (int mf = 0; mf < 2; mf++)
#pragma unroll
            for (int j = 0; j < 4; j++)
#pragma unroll
                for (int r = 0; r < 4; r++) sacc[mf][j][r] = 0.f;

#pragma unroll
        for (int ks = 0; ks < 4; ks++) {
#pragma unroll
            for (int jp = 0; jp < 2; jp++) {
                const uint32_t rb = st +
                    (kw * 32 + jp * 16 + laneRowB) * AT_PITCH +
                    (ks * 2 + chB) * 16;
                uint32_t kh4[4], kl4[4];
                ldm4(kh4, rb);
                ldm4(kl4, rb + AT_TILE);
#pragma unroll
                for (int mf = 0; mf < 2; mf++) {
                    mma16(sacc[mf][jp * 2],     qh[mf][ks], &kh4[0]);
                    mma16(sacc[mf][jp * 2 + 1], qh[mf][ks], &kh4[2]);
                    mma16(sacc[mf][jp * 2],     qh[mf][ks], &kl4[0]);
                    mma16(sacc[mf][jp * 2 + 1], qh[mf][ks], &kl4[2]);
                    mma16(sacc[mf][jp * 2],     ql[mf][ks], &kh4[0]);
                    mma16(sacc[mf][jp * 2 + 1], ql[mf][ks], &kh4[2]);
                }
            }
        }

        // causal mask (diagonal tile only)
        if (tt == T - 1) {
            const int kvb = tt * 64;
#pragma unroll
            for (int mf = 0; mf < 2; mf++) {
                const int rowa = q0 + wq0 + mf * 16 + g;
                const int rowb = rowa + 8;
#pragma unroll
                for (int j = 0; j < 4; j++) {
                    const int c0 = kvb + kw * 32 + j * 8 + t * 2;
                    if (c0 > rowa) sacc[mf][j][0] = -1e30f;
                    if (c0 + 1 > rowa) sacc[mf][j][1] = -1e30f;
                    if (c0 > rowb) sacc[mf][j][2] = -1e30f;
                    if (c0 + 1 > rowb) sacc[mf][j][3] = -1e30f;
                }
            }
        }

        // online softmax per m-frag (own kv half; exp2 domain; rescale-skip)
        uint32_t ph[2][2][4], pl[2][2][4];
#pragma unroll
        for (int mf = 0; mf < 2; mf++) {
            float mxa = -1e30f, mxb = -1e30f;
#pragma unroll
            for (int j = 0; j < 4; j++) {
                mxa = fmaxf(mxa, fmaxf(sacc[mf][j][0], sacc[mf][j][1]));
                mxb = fmaxf(mxb, fmaxf(sacc[mf][j][2], sacc[mf][j][3]));
            }
            mxa = fmaxf(mxa, __shfl_xor_sync(0xffffffffu, mxa, 1));
            mxa = fmaxf(mxa, __shfl_xor_sync(0xffffffffu, mxa, 2));
            mxb = fmaxf(mxb, __shfl_xor_sync(0xffffffffu, mxb, 1));
            mxb = fmaxf(mxb, __shfl_xor_sync(0xffffffffu, mxb, 2));
            const int up = __any_sync(0xffffffffu,
                                      (mxa > m_[mf][0]) || (mxb > m_[mf][1]));
            const float mna = fmaxf(m_[mf][0], mxa);
            const float mnb = fmaxf(m_[mf][1], mxb);

            float ra = 0.f, rb = 0.f;
#pragma unroll
            for (int j = 0; j < 4; j++) {
                const float p0 = ex2(sacc[mf][j][0] - mna);
                const float p1 = ex2(sacc[mf][j][1] - mna);
                const float p2 = ex2(sacc[mf][j][2] - mnb);
                const float p3 = ex2(sacc[mf][j][3] - mnb);
                ra += p0 + p1;
                rb += p2 + p3;
                uint32_t h01, l01, h23, l23;
                split2(p0, p1, h01, l01);
                split2(p2, p3, h23, l23);
                const int kc = j >> 1, half = (j & 1) * 2;
                ph[mf][kc][half] = h01;
                ph[mf][kc][half + 1] = h23;
                pl[mf][kc][half] = l01;
                pl[mf][kc][half + 1] = l23;
            }
            ra += __shfl_xor_sync(0xffffffffu, ra, 1);
            ra += __shfl_xor_sync(0xffffffffu, ra, 2);
            rb += __shfl_xor_sync(0xffffffffu, rb, 1);
            rb += __shfl_xor_sync(0xffffffffu, rb, 2);

            if (up) {
                const float ca = ex2(m_[mf][0] - mna);
                const float cb = ex2(m_[mf][1] - mnb);
                m_[mf][0] = mna;
                m_[mf][1] = mnb;
                l_[mf][0] = l_[mf][0] * ca + ra;
                l_[mf][1] = l_[mf][1] * cb + rb;
#pragma unroll
                for (int j = 0; j < 8; j++) {
                    oacc[mf][j][0] *= ca;
                    oacc[mf][j][1] *= ca;
                    oacc[mf][j][2] *= cb;
                    oacc[mf][j][3] *= cb;
                }
            } else {
                l_[mf][0] += ra;
                l_[mf][1] += rb;
            }
        }

        // O += P V over own kv half (32 rows of V)
        const uint32_t vbase = st + 2 * AT_TILE;
#pragma unroll
        for (int kc = 0; kc < 2; kc++) {
#pragma unroll
            for (int jp = 0; jp < 4; jp++) {
                const uint32_t va = vbase +
                    (kw * 32 + kc * 16 + (lane & 15)) * AT_PITCH +
                    (jp * 16 + (lane >> 4) * 8) * 2;
                uint32_t vh4[4], vl4[4];
                ldm4t(vh4, va);
                ldm4t(vl4, va + AT_TILE);
#pragma unroll
                for (int mf = 0; mf < 2; mf++) {
                    mma16(oacc[mf][jp * 2],     ph[mf][kc], &vh4[0]);
                    mma16(oacc[mf][jp * 2 + 1], ph[mf][kc], &vh4[2]);
                    mma16(oacc[mf][jp * 2],     ph[mf][kc], &vl4[0]);
                    mma16(oacc[mf][jp * 2 + 1], ph[mf][kc], &vl4[2]);
                    mma16(oacc[mf][jp * 2],     pl[mf][kc], &vh4[0]);
                    mma16(oacc[mf][jp * 2 + 1], pl[mf][kc], &vh4[2]);
                }
            }
        }
        __syncthreads();
    }

    // -------- split-KV combine (once per CTA) via dead Q smem region --------
    float* exm = (float*)dsm;            // [2 kw][64 rows]
    float* exl = exm + 128;
    float* ob  = exl + 128;              // [64 rows][OBP]

    if (t == 0) {
#pragma unroll
        for (int mf = 0; mf < 2; mf++)
#pragma unroll
            for (int ab = 0; ab < 2; ab++) {
                const int r = wq0 + mf * 16 + g + ab * 8;
                exm[kw * 64 + r] = m_[mf][ab];
                exl[kw * 64 + r] = l_[mf][ab];
            }
    }
    __syncthreads();

    float sc_[2][2], linv[2][2];
#pragma unroll
    for (int mf = 0; mf < 2; mf++)
#pragma unroll
        for (int ab = 0; ab < 2; ab++) {
            const int r = wq0 + mf * 16 + g + ab * 8;
            const float mo = m_[mf][ab];
            const float mp = exm[(kw ^ 1) * 64 + r];
            const float lp = exl[(kw ^ 1) * 64 + r];
            const float mj = fmaxf(mo, mp);
            const float so = ex2(mo - mj), sp = ex2(mp - mj);
            sc_[mf][ab] = so;
            linv[mf][ab] = 1.f / (l_[mf][ab] * so + lp * sp);
        }

    if (kw == 0) {
#pragma unroll
        for (int mf = 0; mf < 2; mf++)
#pragma unroll
            for (int j = 0; j < 8; j++) {
                const int r0 = wq0 + mf * 16 + g, r1 = r0 + 8;
                const int col = j * 8 + t * 2;
                ob[r0 * OBP + col]     = oacc[mf][j][0] * sc_[mf][0];
                ob[r0 * OBP + col + 1] = oacc[mf][j][1] * sc_[mf][0];
                ob[r1 * OBP + col]     = oacc[mf][j][2] * sc_[mf][1];
                ob[r1 * OBP + col + 1] = oacc[mf][j][3] * sc_[mf][1];
            }
    }
    __syncthreads();
    if (kw == 1) {
#pragma unroll
        for (int mf = 0; mf < 2; mf++)
#pragma unroll
            for (int j = 0; j < 8; j++) {
                const int r0 = wq0 + mf * 16 + g, r1 = r0 + 8;
                const int col = j * 8 + t * 2;
                ob[r0 * OBP + col]     += oacc[mf][j][0] * sc_[mf][0];
                ob[r0 * OBP + col + 1] += oacc[mf][j][1] * sc_[mf][0];
                ob[r1 * OBP + col]     += oacc[mf][j][2] * sc_[mf][1];
                ob[r1 * OBP + col + 1] += oacc[mf][j][3] * sc_[mf][1];
            }
    }
    __syncthreads();

    // write merged-head pre-split output; each warp writes its kw half of cols
    const int b = bh >> 4, h = bh & 15;
#pragma unroll
    for (int mf = 0; mf < 2; mf++)
#pragma unroll
        for (int ab = 0; ab < 2; ab++) {
            const int r = wq0 + mf * 16 + g + ab * 8;
            const float li = linv[mf][ab];
            const int mo = (b * Ssz + q0 + r) * Esz + h * HDd;
#pragma unroll
            for (int j2 = 0; j2 < 4; j2++) {
                const int col = kw * 32 + j2 * 8 + t * 2;
                const float v0 = ob[r * OBP + col] * li;
                const float v1 = ob[r * OBP + col + 1] * li;
                uint32_t hi, lo;
                split2(v0, v1, hi, lo);
                *(uint32_t*)(sOh + mo + col) = hi;
                *(uint32_t*)(sOl + mo + col) = lo;
            }
        }
}

// ---------------------------------------------------------------------------
extern "C" void kernel_launch(void* const* d_in, const int* in_sizes, int n_in,
                              void* d_out, int out_size) {
    const float* x = (const float*)d_in[0];
    const float* w_qkv = (const float*)d_in[1];
    const float* b_qkv = (const float*)d_in[2];
    const float* w_proj = (const float*)d_in[3];
    const float* b_proj = (const float*)d_in[4];
    float* out = (float*)d_out;

    static bool attr_done = false;
    if (!attr_done) {
        cudaFuncSetAttribute(gemm_qkv, cudaFuncAttributeMaxDynamicSharedMemorySize, SMEM_DYN);
        cudaFuncSetAttribute(gemm_proj, cudaFuncAttributeMaxDynamicSharedMemorySize, SMEM_DYN);
        cudaFuncSetAttribute(attn_tc, cudaFuncAttributeMaxDynamicSharedMemorySize, AT_SMEM);
        attr_done = true;
    }

    split_plain<<<Msz * Esz / 4 / 256, 256>>>((const float4*)x);
    split_w_all<<<dim3(128, 32), 256>>>(w_qkv, w_proj);
    gemm_qkv<<<dim3(NQKV / 128, Msz / 128), 256, SMEM_DYN>>>(b_qkv);
    attn_tc<<<dim3(Ssz / 64, Bsz * Hsz), 128, AT_SMEM>>>();
    gemm_proj<<<dim3(Esz / 128, Msz / 128), 256, SMEM_DYN>>>(b_proj, out);
}

// round 16
// speedup vs baseline: 1.0191x; 1.0032x over previous
#include <cuda_runtime.h>
#include <cuda_bf16.h>
#include <cstdint>

// Problem constants
#define Bsz 2
#define Ssz 2048
#define Esz 1024
#define Hsz 16
#define HDd 64
#define Msz (Bsz * Ssz)      // 4096
#define NQKV (3 * Esz)       // 3072

// Q pre-scale: 1/sqrt(64) * log2(e)  (softmax runs in exp2 domain)
#define QSC 0.1803368801111244f

// bf16 hi/lo pre-split operands for the dense GEMMs
__device__ __nv_bfloat16 sXh[Msz * Esz], sXl[Msz * Esz];            // [m][k]
__device__ __nv_bfloat16 sWqh[NQKV * Esz], sWql[NQKV * Esz];        // [n][k]
__device__ __nv_bfloat16 sWph[Esz * Esz], sWpl[Esz * Esz];          // [n][k]
__device__ __nv_bfloat16 sOh[Msz * Esz], sOl[Msz * Esz];            // [m][k] merged heads

// bf16 hi/lo head-split Q/K/V: [B*H][S][64] (Q pre-scaled by QSC)
__device__ __nv_bfloat16 bQh[Bsz * Hsz * Ssz * HDd], bQl[Bsz * Hsz * Ssz * HDd];
__device__ __nv_bfloat16 bKh[Bsz * Hsz * Ssz * HDd], bKl[Bsz * Hsz * Ssz * HDd];
__device__ __nv_bfloat16 bVh[Bsz * Hsz * Ssz * HDd], bVl[Bsz * Hsz * Ssz * HDd];

// ---------------------------------------------------------------------------
// helpers
// ---------------------------------------------------------------------------
__device__ __forceinline__ void split2(float x0, float x1, uint32_t& hi, uint32_t& lo) {
    __nv_bfloat162 h = __floats2bfloat162_rn(x0, x1);
    float r0 = x0 - __bfloat162float(__low2bfloat16(h));
    float r1 = x1 - __bfloat162float(__high2bfloat16(h));
    __nv_bfloat162 l = __floats2bfloat162_rn(r0, r1);
    hi = *(uint32_t*)&h;
    lo = *(uint32_t*)&l;
}

__device__ __forceinline__ float ex2(float x) {
    float y;
    asm("ex2.approx.f32 %0, %1;" : "=f"(y) : "f"(x));
    return y;
}

__device__ __forceinline__ void mma16(float* d, const uint32_t* a, const uint32_t* b) {
    asm volatile(
        "mma.sync.aligned.m16n8k16.row.col.f32.bf16.bf16.f32 "
        "{%0,%1,%2,%3}, {%4,%5,%6,%7}, {%8,%9}, {%0,%1,%2,%3};"
        : "+f"(d[0]), "+f"(d[1]), "+f"(d[2]), "+f"(d[3])
        : "r"(a[0]), "r"(a[1]), "r"(a[2]), "r"(a[3]), "r"(b[0]), "r"(b[1]));
}

__device__ __forceinline__ void ldm4(uint32_t* r, uint32_t addr) {
    asm volatile("ldmatrix.sync.aligned.m8n8.x4.shared.b16 {%0,%1,%2,%3}, [%4];"
                 : "=r"(r[0]), "=r"(r[1]), "=r"(r[2]), "=r"(r[3]) : "r"(addr));
}

__device__ __forceinline__ void ldm4t(uint32_t* r, uint32_t addr) {
    asm volatile("ldmatrix.sync.aligned.m8n8.x4.trans.shared.b16 {%0,%1,%2,%3}, [%4];"
                 : "=r"(r[0]), "=r"(r[1]), "=r"(r[2]), "=r"(r[3]) : "r"(addr));
}

__device__ __forceinline__ void cp16(uint32_t dst, const void* src) {
    asm volatile("cp.async.cg.shared.global [%0], [%1], 16;"
                 :: "r"(dst), "l"(src));
}
#define CP_COMMIT() asm volatile("cp.async.commit_group;" ::: "memory")
#define CP_WAIT(n)  asm volatile("cp.async.wait_group %0;" :: "n"(n) : "memory")

__device__ __forceinline__ uint32_t smem_u32(const void* p) {
    uint32_t a;
    asm("{ .reg .u64 t; cvta.to.shared.u64 t, %1; cvt.u32.u64 %0, t; }"
        : "=r"(a) : "l"(p));
    return a;
}

// ---------------------------------------------------------------------------
// Dense GEMM machinery v2: CTA 128x128, BK=32, 128 threads = 4 warps (2m x 2n),
// warp tile 64x64. LDSM traffic per FLOP is 2/3 of the 8-warp 64x32 layout.
// pitch-80 smem, cp.async double buffer, bf16x3.
// ---------------------------------------------------------------------------
#define TILE_B 10240            // 128 * 80
#define STAGE_B (4 * TILE_B)    // 40960
#define SMEM_DYN (2 * STAGE_B)  // 81920

__device__ __forceinline__ void load_stage(
    uint32_t sbst, const __nv_bfloat16* Ah, const __nv_bfloat16* Al,
    const __nv_bfloat16* Bh, const __nv_bfloat16* Bl,
    int m0, int n0, int k0, int tid) {
#pragma unroll
    for (int g = 0; g < 4; g++) {
        const int idx = g * 128 + tid;
        const int row = idx >> 2, ch = idx & 3;
        const uint32_t d = sbst + row * 80 + ch * 16;
        const int aoff = (m0 + row) * Esz + k0 + ch * 8;
        const int boff = (n0 + row) * Esz + k0 + ch * 8;
        cp16(d, Ah + aoff);
        cp16(d + TILE_B, Al + aoff);
        cp16(d + 2 * TILE_B, Bh + boff);
        cp16(d + 3 * TILE_B, Bl + boff);
    }
}

__device__ __forceinline__ void mma_stage(float acc[4][8][4], uint32_t sbst,
                                          int wm0, int wn0, int lane) {
    const int laneRowA = ((lane >> 3) & 1) * 8 + (lane & 7);
    const int chA = lane >> 4;
    const int laneRowB = (lane >> 4) * 8 + (lane & 7);
    const int chB = (lane >> 3) & 1;
#pragma unroll
    for (int ks = 0; ks < 2; ks++) {
        uint32_t ah[4][4], al[4][4], bh[4][4], bl[4][4];
#pragma unroll
        for (int i = 0; i < 4; i++) {
            const uint32_t ra =
                sbst + (wm0 + i * 16 + laneRowA) * 80 + (ks * 2 + chA) * 16;
            ldm4(ah[i], ra);
            ldm4(al[i], ra + TILE_B);
        }
#pragma unroll
        for (int jp = 0; jp < 4; jp++) {
            const uint32_t rb = sbst + 2 * TILE_B +
                (wn0 + jp * 16 + laneRowB) * 80 + (ks * 2 + chB) * 16;
            ldm4(bh[jp], rb);
            ldm4(bl[jp], rb + TILE_B);
        }
#pragma unroll
        for (int i = 0; i < 4; i++)
#pragma unroll
            for (int j = 0; j < 8; j++)
                mma16(acc[i][j], ah[i], &bh[j >> 1][(j & 1) * 2]);
#pragma unroll
        for (int i = 0; i < 4; i++)
#pragma unroll
            for (int j = 0; j < 8; j++)
                mma16(acc[i][j], ah[i], &bl[j >> 1][(j & 1) * 2]);
#pragma unroll
        for (int i = 0; i < 4; i++)
#pragma unroll
            for (int j = 0; j < 8; j++)
                mma16(acc[i][j], al[i], &bh[j >> 1][(j & 1) * 2]);
    }
}

#define GEMM_MAINLOOP(Ah, Al, Bh, Bl)                                        \
    extern __shared__ char dsm[];                                            \
    const uint32_t sb = smem_u32(dsm);                                       \
    const int tid = threadIdx.x;                                             \
    const int wid = tid >> 5, lane = tid & 31;                               \
    const int wm0 = (wid >> 1) * 64, wn0 = (wid & 1) * 64;                   \
    const int m0 = blockIdx.y * 128, n0 = blockIdx.x * 128;                  \
    float acc[4][8][4];                                                      \
    _Pragma("unroll") for (int i = 0; i < 4; i++)                            \
        _Pragma("unroll") for (int j = 0; j < 8; j++)                        \
            _Pragma("unroll") for (int r = 0; r < 4; r++) acc[i][j][r] = 0.f;\
    load_stage(sb, Ah, Al, Bh, Bl, m0, n0, 0, tid);                          \
    CP_COMMIT();                                                             \
    for (int s = 0; s < Esz / 32; s++) {                                     \
        CP_WAIT(0);                                                          \
        __syncthreads();                                                     \
        if (s + 1 < Esz / 32) {                                              \
            load_stage(sb + ((s + 1) & 1) * STAGE_B, Ah, Al, Bh, Bl,         \
                       m0, n0, (s + 1) * 32, tid);                           \
            CP_COMMIT();                                                     \
        }                                                                    \
        mma_stage(acc, sb + (s & 1) * STAGE_B, wm0, wn0, lane);              \
    }

// ---------------------------------------------------------------------------
// Kernel 1: qkv GEMM; epilogue writes pre-split bf16 Q/K/V (Q scaled QSC)
// ---------------------------------------------------------------------------
__global__ __launch_bounds__(128, 2) void gemm_qkv(const float* __restrict__ bias) {
    GEMM_MAINLOOP(sXh, sXl, sWqh, sWql)

    const int g2 = lane >> 2, t2 = lane & 3;
#pragma unroll
    for (int i = 0; i < 4; i++) {
#pragma unroll
        for (int j = 0; j < 8; j++) {
            const int r0 = m0 + wm0 + i * 16 + g2;
            const int c0 = n0 + wn0 + j * 8 + t2 * 2;
            const int part = c0 >> 10, e = c0 & 1023;
            const int hh = e >> 6, d = e & 63;
            __nv_bfloat16 *dh, *dl;
            if (part == 0)      { dh = bQh; dl = bQl; }
            else if (part == 1) { dh = bKh; dl = bKl; }
            else                { dh = bVh; dl = bVl; }
            const float sc = (part == 0) ? QSC : 1.f;
            const float bb0 = bias[c0], bb1 = bias[c0 + 1];
            {
                const int b = r0 >> 11, sq = r0 & 2047;
                const int off = (((b << 4) + hh) * Ssz + sq) * HDd + d;
                uint32_t hi, lo;
                split2((acc[i][j][0] + bb0) * sc, (acc[i][j][1] + bb1) * sc, hi, lo);
                *(uint32_t*)(dh + off) = hi;
                *(uint32_t*)(dl + off) = lo;
            }
            {
                const int r1 = r0 + 8;
                const int b = r1 >> 11, sq = r1 & 2047;
                const int off = (((b << 4) + hh) * Ssz + sq) * HDd + d;
                uint32_t hi, lo;
                split2((acc[i][j][2] + bb0) * sc, (acc[i][j][3] + bb1) * sc, hi, lo);
                *(uint32_t*)(dh + off) = hi;
                *(uint32_t*)(dl + off) = lo;
            }
        }
    }
}

// ---------------------------------------------------------------------------
// Kernel 3: proj GEMM -> d_out
// ---------------------------------------------------------------------------
__global__ __launch_bounds__(128, 2) void gemm_proj(const float* __restrict__ bias,
                                                    float* __restrict__ out) {
    GEMM_MAINLOOP(sOh, sOl, sWph, sWpl)

    const int g2 = lane >> 2, t2 = lane & 3;
#pragma unroll
    for (int i = 0; i < 4; i++) {
#pragma unroll
        for (int j = 0; j < 8; j++) {
            const int r0 = m0 + wm0 + i * 16 + g2;
            const int c0 = n0 + wn0 + j * 8 + t2 * 2;
            const float b0 = bias[c0], b1 = bias[c0 + 1];
            float2 v0 = make_float2(acc[i][j][0] + b0, acc[i][j][1] + b1);
            float2 v1 = make_float2(acc[i][j][2] + b0, acc[i][j][3] + b1);
            *(float2*)(out + r0 * Esz + c0) = v0;
            *(float2*)(out + (r0 + 8) * Esz + c0) = v1;
        }
    }
}

// ---------------------------------------------------------------------------
// Pre-split kernels: X (plain) and both weights (merged transpose kernel)
// ---------------------------------------------------------------------------
__global__ __launch_bounds__(256) void split_plain(const float4* __restrict__ src) {
    const int i = blockIdx.x * 256 + threadIdx.x;
    const float4 v = src[i];
    uint32_t h0, l0, h1, l1;
    split2(v.x, v.y, h0, l0);
    split2(v.z, v.w, h1, l1);
    ((uint2*)sXh)[i] = make_uint2(h0, h1);
    ((uint2*)sXl)[i] = make_uint2(l0, l1);
}

__global__ __launch_bounds__(256) void split_w_all(const float* __restrict__ Wq,
                                                   const float* __restrict__ Wp) {
    __shared__ float tbuf[32][33];
    const float* W;
    __nv_bfloat16 *Th, *Tl;
    int N, nblk;
    if (blockIdx.x < 96) { W = Wq; Th = sWqh; Tl = sWql; N = NQKV; nblk = blockIdx.x; }
    else                 { W = Wp; Th = sWph; Tl = sWpl; N = Esz;  nblk = blockIdx.x - 96; }
    const int k0 = blockIdx.y * 32, n0 = nblk * 32;
    const int tx = threadIdx.x & 31, ty = threadIdx.x >> 5;
#pragma unroll
    for (int r = ty; r < 32; r += 8)
        tbuf[r][tx] = W[(k0 + r) * N + n0 + tx];
    __syncthreads();
#pragma unroll
    for (int r = ty; r < 32; r += 8) {
        const float v = tbuf[tx][r];
        __nv_bfloat16 h = __float2bfloat16_rn(v);
        __nv_bfloat16 l = __float2bfloat16_rn(v - __bfloat162float(h));
        Th[(n0 + r) * Esz + k0 + tx] = h;
        Tl[(n0 + r) * Esz + k0 + tx] = l;
    }
}

// ---------------------------------------------------------------------------
// Kernel 2: tensor-core causal flash attention, SPLIT-KV (exact round-13
// version, best measured). 128 threads, warp (mw,kw); mw owns 32 q-rows,
// kw owns a 32-col kv half; end-of-kernel split-KV combine via dead Q smem.
// ---------------------------------------------------------------------------
#define AT_PITCH 144
#define AT_TILE (64 * AT_PITCH)              // 9216
#define AT_STAGE0 (2 * AT_TILE)              // Q hi/lo region (dead after tt=0)
#define AT_STAGE_B (4 * AT_TILE)             // 36864
#define AT_SMEM (AT_STAGE0 + 2 * AT_STAGE_B) // 92160
#define OBP 68                               // O-combine row pitch (floats)

__device__ __forceinline__ void at_load_kv(uint32_t st, int base, int kv0, int tid) {
#pragma unroll
    for (int gq = 0; gq < 4; gq++) {
        const int idx = gq * 128 + tid;          // 0..511
        const int row = idx >> 3, ch = idx & 7;
        const uint32_t d = st + row * AT_PITCH + ch * 16;
        const int off = base + (kv0 + row) * HDd + ch * 8;
        cp16(d, bKh + off);
        cp16(d + AT_TILE, bKl + off);
        cp16(d + 2 * AT_TILE, bVh + off);
        cp16(d + 3 * AT_TILE, bVl + off);
    }
}

__global__ __launch_bounds__(128, 2) void attn_tc() {
    extern __shared__ char dsm[];
    const uint32_t sb = smem_u32(dsm);
    const int tid = threadIdx.x, wid = tid >> 5, lane = tid & 31;
    const int mw = wid >> 1;            // q-row half
    const int kw = wid & 1;             // kv half
    const int bh = blockIdx.y;
    const int q0 = (gridDim.x - 1 - blockIdx.x) * 64;  // heavy tiles first
    const int wq0 = mw * 32;
    const int g = lane >> 2, t = lane & 3;
    const int base = bh * Ssz * HDd;

    // async: Q tile hi/lo (64 rows)
#pragma unroll
    for (int gq = 0; gq < 4; gq++) {
        const int idx = gq * 128 + tid;
        const int row = idx >> 3, ch = idx & 7;
        const uint32_t d = sb + row * AT_PITCH + ch * 16;
        const int off = base + (q0 + row) * HDd + ch * 8;
        cp16(d, bQh + off);
        cp16(d + AT_TILE, bQl + off);
    }
    at_load_kv(sb + AT_STAGE0, base, 0, tid);
    CP_COMMIT();

    const int T = q0 / 64 + 1;

    float oacc[2][8][4];
#pragma unroll
    for (int mf = 0; mf < 2; mf++)
#pragma unroll
        for (int j = 0; j < 8; j++)
#pragma unroll
            for (int r = 0; r < 4; r++) oacc[mf][j][r] = 0.f;
    float m_[2][2] = {{-1e30f, -1e30f}, {-1e30f, -1e30f}};
    float l_[2][2] = {{0.f, 0.f}, {0.f, 0.f}};
    uint32_t qh[2][4][4], ql[2][4][4];

    const int laneRowB = (lane >> 4) * 8 + (lane & 7);
    const int chB = (lane >> 3) & 1;

    for (int tt = 0; tt < T; tt++) {
        if (tt + 1 < T) {
            at_load_kv(sb + AT_STAGE0 + ((tt + 1) & 1) * AT_STAGE_B,
                       base, (tt + 1) * 64, tid);
            CP_COMMIT();
            CP_WAIT(1);
        } else {
            CP_WAIT(0);
        }
        __syncthreads();

        if (tt == 0) {
#pragma unroll
            for (int mf = 0; mf < 2; mf++)
#pragma unroll
                for (int ks = 0; ks < 4; ks++) {
                    const uint32_t ra = sb +
                        (wq0 + mf * 16 + (lane & 15)) * AT_PITCH +
                        (ks * 2 + (lane >> 4)) * 16;
                    ldm4(qh[mf][ks], ra);
                    ldm4(ql[mf][ks], ra + AT_TILE);
                }
        }

        const uint32_t st = sb + AT_STAGE0 + (tt & 1) * AT_STAGE_B;

        // S = Q K^T over own kv half (32 cols)
        float sacc[2][4][4];
#pragma unroll
        for (int mf = 0; mf < 2; mf++)
#pragma unroll
            for (int j = 0; j < 4; j++)
#pragma unroll
                for (int r = 0; r < 4; r++) sacc[mf][j][r] = 0.f;

#pragma unroll
        for (int ks = 0; ks < 4; ks++) {
#pragma unroll
            for (int jp = 0; jp < 2; jp++) {
                const uint32_t rb = st +
                    (kw * 32 + jp * 16 + laneRowB) * AT_PITCH +
                    (ks * 2 + chB) * 16;
                uint32_t kh4[4], kl4[4];
                ldm4(kh4, rb);
                ldm4(kl4, rb + AT_TILE);
#pragma unroll
                for (int mf = 0; mf < 2; mf++) {
                    mma16(sacc[mf][jp * 2],     qh[mf][ks], &kh4[0]);
                    mma16(sacc[mf][jp * 2 + 1], qh[mf][ks], &kh4[2]);
                    mma16(sacc[mf][jp * 2],     qh[mf][ks], &kl4[0]);
                    mma16(sacc[mf][jp * 2 + 1], qh[mf][ks], &kl4[2]);
                    mma16(sacc[mf][jp * 2],     ql[mf][ks], &kh4[0]);
                    mma16(sacc[mf][jp * 2 + 1], ql[mf][ks], &kh4[2]);
                }
            }
        }

        // causal mask (diagonal tile only)
        if (tt == T - 1) {
            const int kvb = tt * 64;
#pragma unroll
            for (int mf = 0; mf < 2; mf++) {
                const int rowa = q0 + wq0 + mf * 16 + g;
                const int rowb = rowa + 8;
#pragma unroll
                for (int j = 0; j < 4; j++) {
                    const int c0 = kvb + kw * 32 + j * 8 + t * 2;
                    if (c0 > rowa) sacc[mf][j][0] = -1e30f;
                    if (c0 + 1 > rowa) sacc[mf][j][1] = -1e30f;
                    if (c0 > rowb) sacc[mf][j][2] = -1e30f;
                    if (c0 + 1 > rowb) sacc[mf][j][3] = -1e30f;
                }
            }
        }

        // online softmax per m-frag (own kv half only; exp2 domain)
        uint32_t ph[2][2][4], pl[2][2][4];
#pragma unroll
        for (int mf = 0; mf < 2; mf++) {
            float mxa = -1e30f, mxb = -1e30f;
#pragma unroll
            for (int j = 0; j < 4; j++) {
                mxa = fmaxf(mxa, fmaxf(sacc[mf][j][0], sacc[mf][j][1]));
                mxb = fmaxf(mxb, fmaxf(sacc[mf][j][2], sacc[mf][j][3]));
            }
            mxa = fmaxf(mxa, __shfl_xor_sync(0xffffffffu, mxa, 1));
            mxa = fmaxf(mxa, __shfl_xor_sync(0xffffffffu, mxa, 2));
            mxb = fmaxf(mxb, __shfl_xor_sync(0xffffffffu, mxb, 1));
            mxb = fmaxf(mxb, __shfl_xor_sync(0xffffffffu, mxb, 2));
            const float mna = fmaxf(m_[mf][0], mxa);
            const float mnb = fmaxf(m_[mf][1], mxb);
            const float ca = ex2(m_[mf][0] - mna), cb = ex2(m_[mf][1] - mnb);
            m_[mf][0] = mna;
            m_[mf][1] = mnb;

            float ra = 0.f, rb = 0.f;
#pragma unroll
            for (int j = 0; j < 4; j++) {
                const float p0 = ex2(sacc[mf][j][0] - mna);
                const float p1 = ex2(sacc[mf][j][1] - mna);
                const float p2 = ex2(sacc[mf][j][2] - mnb);
                const float p3 = ex2(sacc[mf][j][3] - mnb);
                ra += p0 + p1;
                rb += p2 + p3;
                uint32_t h01, l01, h23, l23;
                split2(p0, p1, h01, l01);
                split2(p2, p3, h23, l23);
                const int kc = j >> 1, half = (j & 1) * 2;
                ph[mf][kc][half] = h01;
                ph[mf][kc][half + 1] = h23;
                pl[mf][kc][half] = l01;
                pl[mf][kc][half + 1] = l23;
            }
            ra += __shfl_xor_sync(0xffffffffu, ra, 1);
            ra += __shfl_xor_sync(0xffffffffu, ra, 2);
            rb += __shfl_xor_sync(0xffffffffu, rb, 1);
            rb += __shfl_xor_sync(0xffffffffu, rb, 2);
            l_[mf][0] = l_[mf][0] * ca + ra;
            l_[mf][1] = l_[mf][1] * cb + rb;

#pragma unroll
            for (int j = 0; j < 8; j++) {
                oacc[mf][j][0] *= ca;
                oacc[mf][j][1] *= ca;
                oacc[mf][j][2] *= cb;
                oacc[mf][j][3] *= cb;
            }
        }

        // O += P V over own kv half (32 rows of V)
        const uint32_t vbase = st + 2 * AT_TILE;
#pragma unroll
        for (int kc = 0; kc < 2; kc++) {
#pragma unroll
            for (int jp = 0; jp < 4; jp++) {
                const uint32_t va = vbase +
                    (kw * 32 + kc * 16 + (lane & 15)) * AT_PITCH +
                    (jp * 16 + (lane >> 4) * 8) * 2;
                uint32_t vh4[4], vl4[4];
                ldm4t(vh4, va);
                ldm4t(vl4, va + AT_TILE);
#pragma unroll
                for (int mf = 0; mf < 2; mf++) {
                    mma16(oacc[mf][jp * 2],     ph[mf][kc], &vh4[0]);
                    mma16(oacc[mf][jp * 2 + 1], ph[mf][kc], &vh4[2]);
                    mma16(oacc[mf][jp * 2],     ph[mf][kc], &vl4[0]);
                    mma16(oacc[mf][jp * 2 + 1], ph[mf][kc], &vl4[2]);
                    mma16(oacc[mf][jp * 2],     pl[mf][kc], &vh4[0]);
                    mma16(oacc[mf][jp * 2 + 1], pl[mf][kc], &vh4[2]);
                }
            }
        }
        __syncthreads();
    }

    // -------- split-KV combine (once per CTA) via dead Q smem region --------
    float* exm = (float*)dsm;            // [2 kw][64 rows]
    float* exl = exm + 128;
    float* ob  = exl + 128;              // [64 rows][OBP]

    if (t == 0) {
#pragma unroll
        for (int mf = 0; mf < 2; mf++)
#pragma unroll
            for (int ab = 0; ab < 2; ab++) {
                const int r = wq0 + mf * 16 + g + ab * 8;
                exm[kw * 64 + r] = m_[mf][ab];
                exl[kw * 64 + r] = l_[mf][ab];
            }
    }
    __syncthreads();

    float sc_[2][2], linv[2][2];
#pragma unroll
    for (int mf = 0; mf < 2; mf++)
#pragma unroll
        for (int ab = 0; ab < 2; ab++) {
            const int r = wq0 + mf * 16 + g + ab * 8;
            const float mo = m_[mf][ab];
            const float mp = exm[(kw ^ 1) * 64 + r];
            const float lp = exl[(kw ^ 1) * 64 + r];
            const float mj = fmaxf(mo, mp);
            const float so = ex2(mo - mj), sp = ex2(mp - mj);
            sc_[mf][ab] = so;
            linv[mf][ab] = 1.f / (l_[mf][ab] * so + lp * sp);
        }

    if (kw == 0) {
#pragma unroll
        for (int mf = 0; mf < 2; mf++)
#pragma unroll
            for (int j = 0; j < 8; j++) {
                const int r0 = wq0 + mf * 16 + g, r1 = r0 + 8;
                const int col = j * 8 + t * 2;
                ob[r0 * OBP + col]     = oacc[mf][j][0] * sc_[mf][0];
                ob[r0 * OBP + col + 1] = oacc[mf][j][1] * sc_[mf][0];
                ob[r1 * OBP + col]     = oacc[mf][j][2] * sc_[mf][1];
                ob[r1 * OBP + col + 1] = oacc[mf][j][3] * sc_[mf][1];
            }
    }
    __syncthreads();
    if (kw == 1) {
#pragma unroll
        for (int mf = 0; mf < 2; mf++)
#pragma unroll
            for (int j = 0; j < 8; j++) {
                const int r0 = wq0 + mf * 16 + g, r1 = r0 + 8;
                const int col = j * 8 + t * 2;
                ob[r0 * OBP + col]     += oacc[mf][j][0] * sc_[mf][0];
                ob[r0 * OBP + col + 1] += oacc[mf][j][1] * sc_[mf][0];
                ob[r1 * OBP + col]     += oacc[mf][j][2] * sc_[mf][1];
                ob[r1 * OBP + col + 1] += oacc[mf][j][3] * sc_[mf][1];
            }
    }
    __syncthreads();

    // write merged-head pre-split output; each warp writes its kw half of cols
    const int b = bh >> 4, h = bh & 15;
#pragma unroll
    for (int mf = 0; mf < 2; mf++)
#pragma unroll
        for (int ab = 0; ab < 2; ab++) {
            const int r = wq0 + mf * 16 + g + ab * 8;
            const float li = linv[mf][ab];
            const int mo = (b * Ssz + q0 + r) * Esz + h * HDd;
#pragma unroll
            for (int j2 = 0; j2 < 4; j2++) {
                const int col = kw * 32 + j2 * 8 + t * 2;
                const float v0 = ob[r * OBP + col] * li;
                const float v1 = ob[r * OBP + col + 1] * li;
                uint32_t hi, lo;
                split2(v0, v1, hi, lo);
                *(uint32_t*)(sOh + mo + col) = hi;
                *(uint32_t*)(sOl + mo + col) = lo;
            }
        }
}

// ---------------------------------------------------------------------------
extern "C" void kernel_launch(void* const* d_in, const int* in_sizes, int n_in,
                              void* d_out, int out_size) {
    const float* x = (const float*)d_in[0];
    const float* w_qkv = (const float*)d_in[1];
    const float* b_qkv = (const float*)d_in[2];
    const float* w_proj = (const float*)d_in[3];
    const float* b_proj = (const float*)d_in[4];
    float* out = (float*)d_out;

    static bool attr_done = false;
    if (!attr_done) {
        cudaFuncSetAttribute(gemm_qkv, cudaFuncAttributeMaxDynamicSharedMemorySize, SMEM_DYN);
        cudaFuncSetAttribute(gemm_proj, cudaFuncAttributeMaxDynamicSharedMemorySize, SMEM_DYN);
        cudaFuncSetAttribute(attn_tc, cudaFuncAttributeMaxDynamicSharedMemorySize, AT_SMEM);
        attr_done = true;
    }

    split_plain<<<Msz * Esz / 4 / 256, 256>>>((const float4*)x);
    split_w_all<<<dim3(128, 32), 256>>>(w_qkv, w_proj);
    gemm_qkv<<<dim3(NQKV / 128, Msz / 128), 128, SMEM_DYN>>>(b_qkv);
    attn_tc<<<dim3(Ssz / 64, Bsz * Hsz), 128, AT_SMEM>>>();
    gemm_proj<<<dim3(Esz / 128, Msz / 128), 128, SMEM_DYN>>>(b_proj, out);
}

// round 17
// speedup vs baseline: 1.0520x; 1.0323x over previous
#include <cuda_runtime.h>
#include <cuda_bf16.h>
#include <cstdint>

// Problem constants
#define Bsz 2
#define Ssz 2048
#define Esz 1024
#define Hsz 16
#define HDd 64
#define Msz (Bsz * Ssz)      // 4096
#define NQKV (3 * Esz)       // 3072

// Q pre-scale: 1/sqrt(64) * log2(e)  (softmax runs in exp2 domain)
#define QSC 0.1803368801111244f

// bf16 hi/lo pre-split operands for the dense GEMMs
__device__ __nv_bfloat16 sXh[Msz * Esz], sXl[Msz * Esz];            // [m][k]
__device__ __nv_bfloat16 sWqh[NQKV * Esz], sWql[NQKV * Esz];        // [n][k]
__device__ __nv_bfloat16 sWph[Esz * Esz], sWpl[Esz * Esz];          // [n][k]
__device__ __nv_bfloat16 sOh[Msz * Esz], sOl[Msz * Esz];            // [m][k] merged heads

// bf16 hi/lo head-split Q/K/V: [B*H][S][64] (Q pre-scaled by QSC)
__device__ __nv_bfloat16 bQh[Bsz * Hsz * Ssz * HDd], bQl[Bsz * Hsz * Ssz * HDd];
__device__ __nv_bfloat16 bKh[Bsz * Hsz * Ssz * HDd], bKl[Bsz * Hsz * Ssz * HDd];
__device__ __nv_bfloat16 bVh[Bsz * Hsz * Ssz * HDd], bVl[Bsz * Hsz * Ssz * HDd];

// ---------------------------------------------------------------------------
// helpers
// ---------------------------------------------------------------------------
__device__ __forceinline__ void split2(float x0, float x1, uint32_t& hi, uint32_t& lo) {
    __nv_bfloat162 h = __floats2bfloat162_rn(x0, x1);
    float r0 = x0 - __bfloat162float(__low2bfloat16(h));
    float r1 = x1 - __bfloat162float(__high2bfloat16(h));
    __nv_bfloat162 l = __floats2bfloat162_rn(r0, r1);
    hi = *(uint32_t*)&h;
    lo = *(uint32_t*)&l;
}

__device__ __forceinline__ float ex2(float x) {
    float y;
    asm("ex2.approx.f32 %0, %1;" : "=f"(y) : "f"(x));
    return y;
}

__device__ __forceinline__ void mma16(float* d, const uint32_t* a, const uint32_t* b) {
    asm volatile(
        "mma.sync.aligned.m16n8k16.row.col.f32.bf16.bf16.f32 "
        "{%0,%1,%2,%3}, {%4,%5,%6,%7}, {%8,%9}, {%0,%1,%2,%3};"
        : "+f"(d[0]), "+f"(d[1]), "+f"(d[2]), "+f"(d[3])
        : "r"(a[0]), "r"(a[1]), "r"(a[2]), "r"(a[3]), "r"(b[0]), "r"(b[1]));
}

__device__ __forceinline__ void ldm4(uint32_t* r, uint32_t addr) {
    asm volatile("ldmatrix.sync.aligned.m8n8.x4.shared.b16 {%0,%1,%2,%3}, [%4];"
                 : "=r"(r[0]), "=r"(r[1]), "=r"(r[2]), "=r"(r[3]) : "r"(addr));
}

__device__ __forceinline__ void ldm4t(uint32_t* r, uint32_t addr) {
    asm volatile("ldmatrix.sync.aligned.m8n8.x4.trans.shared.b16 {%0,%1,%2,%3}, [%4];"
                 : "=r"(r[0]), "=r"(r[1]), "=r"(r[2]), "=r"(r[3]) : "r"(addr));
}

__device__ __forceinline__ void cp16(uint32_t dst, const void* src) {
    asm volatile("cp.async.cg.shared.global [%0], [%1], 16;"
                 :: "r"(dst), "l"(src));
}
#define CP_COMMIT() asm volatile("cp.async.commit_group;" ::: "memory")
#define CP_WAIT(n)  asm volatile("cp.async.wait_group %0;" :: "n"(n) : "memory")

__device__ __forceinline__ uint32_t smem_u32(const void* p) {
    uint32_t a;
    asm("{ .reg .u64 t; cvta.to.shared.u64 t, %1; cvt.u32.u64 %0, t; }"
        : "=r"(a) : "l"(p));
    return a;
}

// ---------------------------------------------------------------------------
// Dense GEMM machinery: CTA 128x128, BK=32, 256 threads = 8 warps (2m x 4n),
// pitch-80 smem, cp.async double buffer, ldmatrix, bf16x3. Global-load
// addresses are loop-carried byte pointers (+64B/stage).
// ---------------------------------------------------------------------------
#define TILE_B 10240            // 128 * 80
#define STAGE_B (4 * TILE_B)    // 40960
#define SMEM_DYN (2 * STAGE_B)  // 81920
#define GOFF 131072             // 64 rows * 1024 k * 2 B
#define SOFF 5120               // 64 rows * 80 B

#define LOAD_ONE(base)                                                \
    do {                                                              \
        cp16((base) + dsoff, pA);                                     \
        cp16((base) + dsoff + TILE_B, pAl);                           \
        cp16((base) + dsoff + 2 * TILE_B, pB);                        \
        cp16((base) + dsoff + 3 * TILE_B, pBl);                       \
        cp16((base) + dsoff + SOFF, pA + GOFF);                       \
        cp16((base) + dsoff + SOFF + TILE_B, pAl + GOFF);             \
        cp16((base) + dsoff + SOFF + 2 * TILE_B, pB + GOFF);          \
        cp16((base) + dsoff + SOFF + 3 * TILE_B, pBl + GOFF);         \
    } while (0)

__device__ __forceinline__ void mma_stage(float acc[4][4][4], uint32_t sbst,
                                          int wm0, int wn0, int lane) {
    const int laneRowA = ((lane >> 3) & 1) * 8 + (lane & 7);
    const int chA = lane >> 4;
    const int laneRowB = (lane >> 4) * 8 + (lane & 7);
    const int chB = (lane >> 3) & 1;
#pragma unroll
    for (int ks = 0; ks < 2; ks++) {
        uint32_t ah[4][4], al[4][4], bh[2][4], bl[2][4];
#pragma unroll
        for (int i = 0; i < 4; i++) {
            const uint32_t ra =
                sbst + (wm0 + i * 16 + laneRowA) * 80 + (ks * 2 + chA) * 16;
            ldm4(ah[i], ra);
            ldm4(al[i], ra + TILE_B);
        }
#pragma unroll
        for (int jp = 0; jp < 2; jp++) {
            const uint32_t rb = sbst + 2 * TILE_B +
                (wn0 + jp * 16 + laneRowB) * 80 + (ks * 2 + chB) * 16;
            ldm4(bh[jp], rb);
            ldm4(bl[jp], rb + TILE_B);
        }
#pragma unroll
        for (int i = 0; i < 4; i++)
#pragma unroll
            for (int j = 0; j < 4; j++)
                mma16(acc[i][j], ah[i], &bh[j >> 1][(j & 1) * 2]);
#pragma unroll
        for (int i = 0; i < 4; i++)
#pragma unroll
            for (int j = 0; j < 4; j++)
                mma16(acc[i][j], ah[i], &bl[j >> 1][(j & 1) * 2]);
#pragma unroll
        for (int i = 0; i < 4; i++)
#pragma unroll
            for (int j = 0; j < 4; j++)
                mma16(acc[i][j], al[i], &bh[j >> 1][(j & 1) * 2]);
    }
}

#define GEMM_MAINLOOP(Ah, Al, Bh, Bl)                                        \
    extern __shared__ char dsm[];                                            \
    const uint32_t sb = smem_u32(dsm);                                       \
    const int tid = threadIdx.x;                                             \
    const int wid = tid >> 5, lane = tid & 31;                               \
    const int wm0 = (wid >> 2) * 64, wn0 = (wid & 3) * 32;                   \
    const int m0 = blockIdx.y * 128, n0 = blockIdx.x * 128;                  \
    const int ldrow = tid >> 2, ldch = tid & 3;                              \
    const uint32_t dsoff = (uint32_t)(ldrow * 80 + ldch * 16);               \
    const char* pA  = (const char*)((Ah) + (m0 + ldrow) * Esz + ldch * 8);   \
    const char* pAl = (const char*)((Al) + (m0 + ldrow) * Esz + ldch * 8);   \
    const char* pB  = (const char*)((Bh) + (n0 + ldrow) * Esz + ldch * 8);   \
    const char* pBl = (const char*)((Bl) + (n0 + ldrow) * Esz + ldch * 8);   \
    float acc[4][4][4];                                                      \
    _Pragma("unroll") for (int i = 0; i < 4; i++)                            \
        _Pragma("unroll") for (int j = 0; j < 4; j++)                        \
            _Pragma("unroll") for (int r = 0; r < 4; r++) acc[i][j][r] = 0.f;\
    LOAD_ONE(sb);                                                            \
    CP_COMMIT();                                                             \
    pA += 64; pAl += 64; pB += 64; pBl += 64;                                \
    for (int s = 0; s < Esz / 32; s++) {                                     \
        CP_WAIT(0);                                                          \
        __syncthreads();                                                     \
        if (s + 1 < Esz / 32) {                                              \
            LOAD_ONE(sb + ((s + 1) & 1) * STAGE_B);                          \
            CP_COMMIT();                                                     \
            pA += 64; pAl += 64; pB += 64; pBl += 64;                        \
        }                                                                    \
        mma_stage(acc, sb + (s & 1) * STAGE_B, wm0, wn0, lane);              \
    }

// ---------------------------------------------------------------------------
// Kernel 1: qkv GEMM; epilogue writes pre-split bf16 Q/K/V (Q scaled QSC)
// ---------------------------------------------------------------------------
__global__ __launch_bounds__(256, 2) void gemm_qkv(const float* __restrict__ bias) {
    GEMM_MAINLOOP(sXh, sXl, sWqh, sWql)

    const int g2 = lane >> 2, t2 = lane & 3;
#pragma unroll
    for (int i = 0; i < 4; i++) {
#pragma unroll
        for (int j = 0; j < 4; j++) {
            const int r0 = m0 + wm0 + i * 16 + g2;
            const int c0 = n0 + wn0 + j * 8 + t2 * 2;
            const int part = c0 >> 10, e = c0 & 1023;
            const int hh = e >> 6, d = e & 63;
            __nv_bfloat16 *dh, *dl;
            if (part == 0)      { dh = bQh; dl = bQl; }
            else if (part == 1) { dh = bKh; dl = bKl; }
            else                { dh = bVh; dl = bVl; }
            const float sc = (part == 0) ? QSC : 1.f;
            const float bb0 = bias[c0], bb1 = bias[c0 + 1];
            {
                const int b = r0 >> 11, sq = r0 & 2047;
                const int off = (((b << 4) + hh) * Ssz + sq) * HDd + d;
                uint32_t hi, lo;
                split2((acc[i][j][0] + bb0) * sc, (acc[i][j][1] + bb1) * sc, hi, lo);
                *(uint32_t*)(dh + off) = hi;
                *(uint32_t*)(dl + off) = lo;
            }
            {
                const int r1 = r0 + 8;
                const int b = r1 >> 11, sq = r1 & 2047;
                const int off = (((b << 4) + hh) * Ssz + sq) * HDd + d;
                uint32_t hi, lo;
                split2((acc[i][j][2] + bb0) * sc, (acc[i][j][3] + bb1) * sc, hi, lo);
                *(uint32_t*)(dh + off) = hi;
                *(uint32_t*)(dl + off) = lo;
            }
        }
    }
}

// ---------------------------------------------------------------------------
// Kernel 3: proj GEMM -> d_out
// ---------------------------------------------------------------------------
__global__ __launch_bounds__(256, 2) void gemm_proj(const float* __restrict__ bias,
                                                    float* __restrict__ out) {
    GEMM_MAINLOOP(sOh, sOl, sWph, sWpl)

    const int g2 = lane >> 2, t2 = lane & 3;
#pragma unroll
    for (int i = 0; i < 4; i++) {
#pragma unroll
        for (int j = 0; j < 4; j++) {
            const int r0 = m0 + wm0 + i * 16 + g2;
            const int c0 = n0 + wn0 + j * 8 + t2 * 2;
            const float b0 = bias[c0], b1 = bias[c0 + 1];
            float2 v0 = make_float2(acc[i][j][0] + b0, acc[i][j][1] + b1);
            float2 v1 = make_float2(acc[i][j][2] + b0, acc[i][j][3] + b1);
            *(float2*)(out + r0 * Esz + c0) = v0;
            *(float2*)(out + (r0 + 8) * Esz + c0) = v1;
        }
    }
}

// ---------------------------------------------------------------------------
// Pre-split kernels: X (plain) and both weights (merged transpose kernel)
// ---------------------------------------------------------------------------
__global__ __launch_bounds__(256) void split_plain(const float4* __restrict__ src) {
    const int i = blockIdx.x * 256 + threadIdx.x;
    const float4 v = src[i];
    uint32_t h0, l0, h1, l1;
    split2(v.x, v.y, h0, l0);
    split2(v.z, v.w, h1, l1);
    ((uint2*)sXh)[i] = make_uint2(h0, h1);
    ((uint2*)sXl)[i] = make_uint2(l0, l1);
}

__global__ __launch_bounds__(256) void split_w_all(const float* __restrict__ Wq,
                                                   const float* __restrict__ Wp) {
    __shared__ float tbuf[32][33];
    const float* W;
    __nv_bfloat16 *Th, *Tl;
    int N, nblk;
    if (blockIdx.x < 96) { W = Wq; Th = sWqh; Tl = sWql; N = NQKV; nblk = blockIdx.x; }
    else                 { W = Wp; Th = sWph; Tl = sWpl; N = Esz;  nblk = blockIdx.x - 96; }
    const int k0 = blockIdx.y * 32, n0 = nblk * 32;
    const int tx = threadIdx.x & 31, ty = threadIdx.x >> 5;
#pragma unroll
    for (int r = ty; r < 32; r += 8)
        tbuf[r][tx] = W[(k0 + r) * N + n0 + tx];
    __syncthreads();
#pragma unroll
    for (int r = ty; r < 32; r += 8) {
        const float v = tbuf[tx][r];
        __nv_bfloat16 h = __float2bfloat16_rn(v);
        __nv_bfloat16 l = __float2bfloat16_rn(v - __bfloat162float(h));
        Th[(n0 + r) * Esz + k0 + tx] = h;
        Tl[(n0 + r) * Esz + k0 + tx] = l;
    }
}

// ---------------------------------------------------------------------------
// Kernel 2: tensor-core causal flash attention, SPLIT-KV (exact round-13
// version, best measured). 128 threads, warp (mw,kw); mw owns 32 q-rows,
// kw owns a 32-col kv half; end-of-kernel split-KV combine via dead Q smem.
// ---------------------------------------------------------------------------
#define AT_PITCH 144
#define AT_TILE (64 * AT_PITCH)              // 9216
#define AT_STAGE0 (2 * AT_TILE)              // Q hi/lo region (dead after tt=0)
#define AT_STAGE_B (4 * AT_TILE)             // 36864
#define AT_SMEM (AT_STAGE0 + 2 * AT_STAGE_B) // 92160
#define OBP 68                               // O-combine row pitch (floats)

__device__ __forceinline__ void at_load_kv(uint32_t st, int base, int kv0, int tid) {
#pragma unroll
    for (int gq = 0; gq < 4; gq++) {
        const int idx = gq * 128 + tid;          // 0..511
        const int row = idx >> 3, ch = idx & 7;
        const uint32_t d = st + row * AT_PITCH + ch * 16;
        const int off = base + (kv0 + row) * HDd + ch * 8;
        cp16(d, bKh + off);
        cp16(d + AT_TILE, bKl + off);
        cp16(d + 2 * AT_TILE, bVh + off);
        cp16(d + 3 * AT_TILE, bVl + off);
    }
}

__global__ __launch_bounds__(128, 2) void attn_tc() {
    extern __shared__ char dsm[];
    const uint32_t sb = smem_u32(dsm);
    const int tid = threadIdx.x, wid = tid >> 5, lane = tid & 31;
    const int mw = wid >> 1;            // q-row half
    const int kw = wid & 1;             // kv half
    const int bh = blockIdx.y;
    const int q0 = (gridDim.x - 1 - blockIdx.x) * 64;  // heavy tiles first
    const int wq0 = mw * 32;
    const int g = lane >> 2, t = lane & 3;
    const int base = bh * Ssz * HDd;

    // async: Q tile hi/lo (64 rows)
#pragma unroll
    for (int gq = 0; gq < 4; gq++) {
        const int idx = gq * 128 + tid;
        const int row = idx >> 3, ch = idx & 7;
        const uint32_t d = sb + row * AT_PITCH + ch * 16;
        const int off = base + (q0 + row) * HDd + ch * 8;
        cp16(d, bQh + off);
        cp16(d + AT_TILE, bQl + off);
    }
    at_load_kv(sb + AT_STAGE0, base, 0, tid);
    CP_COMMIT();

    const int T = q0 / 64 + 1;

    float oacc[2][8][4];
#pragma unroll
    for (int mf = 0; mf < 2; mf++)
#pragma unroll
        for (int j = 0; j < 8; j++)
#pragma unroll
            for (int r = 0; r < 4; r++) oacc[mf][j][r] = 0.f;
    float m_[2][2] = {{-1e30f, -1e30f}, {-1e30f, -1e30f}};
    float l_[2][2] = {{0.f, 0.f}, {0.f, 0.f}};
    uint32_t qh[2][4][4], ql[2][4][4];

    const int laneRowB = (lane >> 4) * 8 + (lane & 7);
    const int chB = (lane >> 3) & 1;

    for (int tt = 0; tt < T; tt++) {
        if (tt + 1 < T) {
            at_load_kv(sb + AT_STAGE0 + ((tt + 1) & 1) * AT_STAGE_B,
                       base, (tt + 1) * 64, tid);
            CP_COMMIT();
            CP_WAIT(1);
        } else {
            CP_WAIT(0);
        }
        __syncthreads();

        if (tt == 0) {
#pragma unroll
            for (int mf = 0; mf < 2; mf++)
#pragma unroll
                for (int ks = 0; ks < 4; ks++) {
                    const uint32_t ra = sb +
                        (wq0 + mf * 16 + (lane & 15)) * AT_PITCH +
                        (ks * 2 + (lane >> 4)) * 16;
                    ldm4(qh[mf][ks], ra);
                    ldm4(ql[mf][ks], ra + AT_TILE);
                }
        }

        const uint32_t st = sb + AT_STAGE0 + (tt & 1) * AT_STAGE_B;

        // S = Q K^T over own kv half (32 cols)
        float sacc[2][4][4];
#pragma unroll
        for (int mf = 0; mf < 2; mf++)
#pragma unroll
            for (int j = 0; j < 4; j++)
#pragma unroll
                for (int r = 0; r < 4; r++) sacc[mf][j][r] = 0.f;

#pragma unroll
        for (int ks = 0; ks < 4; ks++) {
#pragma unroll
            for (int jp = 0; jp < 2; jp++) {
                const uint32_t rb = st +
                    (kw * 32 + jp * 16 + laneRowB) * AT_PITCH +
                    (ks * 2 + chB) * 16;
                uint32_t kh4[4], kl4[4];
                ldm4(kh4, rb);
                ldm4(kl4, rb + AT_TILE);
#pragma unroll
                for (int mf = 0; mf < 2; mf++) {
                    mma16(sacc[mf][jp * 2],     qh[mf][ks], &kh4[0]);
                    mma16(sacc[mf][jp * 2 + 1], qh[mf][ks], &kh4[2]);
                    mma16(sacc[mf][jp * 2],     qh[mf][ks], &kl4[0]);
                    mma16(sacc[mf][jp * 2 + 1], qh[mf][ks], &kl4[2]);
                    mma16(sacc[mf][jp * 2],     ql[mf][ks], &kh4[0]);
                    mma16(sacc[mf][jp * 2 + 1], ql[mf][ks], &kh4[2]);
                }
            }
        }

        // causal mask (diagonal tile only)
        if (tt == T - 1) {
            const int kvb = tt * 64;
#pragma unroll
            for (int mf = 0; mf < 2; mf++) {
                const int rowa = q0 + wq0 + mf * 16 + g;
                const int rowb = rowa + 8;
#pragma unroll
                for (int j = 0; j < 4; j++) {
                    const int c0 = kvb + kw * 32 + j * 8 + t * 2;
                    if (c0 > rowa) sacc[mf][j][0] = -1e30f;
                    if (c0 + 1 > rowa) sacc[mf][j][1] = -1e30f;
                    if (c0 > rowb) sacc[mf][j][2] = -1e30f;
                    if (c0 + 1 > rowb) sacc[mf][j][3] = -1e30f;
                }
            }
        }

        // online softmax per m-frag (own kv half only; exp2 domain)
        uint32_t ph[2][2][4], pl[2][2][4];
#pragma unroll
        for (int mf = 0; mf < 2; mf++) {
            float mxa = -1e30f, mxb = -1e30f;
#pragma unroll
            for (int j = 0; j < 4; j++) {
                mxa = fmaxf(mxa, fmaxf(sacc[mf][j][0], sacc[mf][j][1]));
                mxb = fmaxf(mxb, fmaxf(sacc[mf][j][2], sacc[mf][j][3]));
            }
            mxa = fmaxf(mxa, __shfl_xor_sync(0xffffffffu, mxa, 1));
            mxa = fmaxf(mxa, __shfl_xor_sync(0xffffffffu, mxa, 2));
            mxb = fmaxf(mxb, __shfl_xor_sync(0xffffffffu, mxb, 1));
            mxb = fmaxf(mxb, __shfl_xor_sync(0xffffffffu, mxb, 2));
            const float mna = fmaxf(m_[mf][0], mxa);
            const float mnb = fmaxf(m_[mf][1], mxb);
            const float ca = ex2(m_[mf][0] - mna), cb = ex2(m_[mf][1] - mnb);
            m_[mf][0] = mna;
            m_[mf][1] = mnb;

            float ra = 0.f, rb = 0.f;
#pragma unroll
            for (int j = 0; j < 4; j++) {
                const float p0 = ex2(sacc[mf][j][0] - mna);
                const float p1 = ex2(sacc[mf][j][1] - mna);
                const float p2 = ex2(sacc[mf][j][2] - mnb);
                const float p3 = ex2(sacc[mf][j][3] - mnb);
                ra += p0 + p1;
                rb += p2 + p3;
                uint32_t h01, l01, h23, l23;
                split2(p0, p1, h01, l01);
                split2(p2, p3, h23, l23);
                const int kc = j >> 1, half = (j & 1) * 2;
                ph[mf][kc][half] = h01;
                ph[mf][kc][half + 1] = h23;
                pl[mf][kc][half] = l01;
                pl[mf][kc][half + 1] = l23;
            }
            ra += __shfl_xor_sync(0xffffffffu, ra, 1);
            ra += __shfl_xor_sync(0xffffffffu, ra, 2);
            rb += __shfl_xor_sync(0xffffffffu, rb, 1);
            rb += __shfl_xor_sync(0xffffffffu, rb, 2);
            l_[mf][0] = l_[mf][0] * ca + ra;
            l_[mf][1] = l_[mf][1] * cb + rb;

#pragma unroll
            for (int j = 0; j < 8; j++) {
                oacc[mf][j][0] *= ca;
                oacc[mf][j][1] *= ca;
                oacc[mf][j][2] *= cb;
                oacc[mf][j][3] *= cb;
            }
        }

        // O += P V over own kv half (32 rows of V)
        const uint32_t vbase = st + 2 * AT_TILE;
#pragma unroll
        for (int kc = 0; kc < 2; kc++) {
#pragma unroll
            for (int jp = 0; jp < 4; jp++) {
                const uint32_t va = vbase +
                    (kw * 32 + kc * 16 + (lane & 15)) * AT_PITCH +
                    (jp * 16 + (lane >> 4) * 8) * 2;
                uint32_t vh4[4], vl4[4];
                ldm4t(vh4, va);
                ldm4t(vl4, va + AT_TILE);
#pragma unroll
                for (int mf = 0; mf < 2; mf++) {
                    mma16(oacc[mf][jp * 2],     ph[mf][kc], &vh4[0]);
                    mma16(oacc[mf][jp * 2 + 1], ph[mf][kc], &vh4[2]);
                    mma16(oacc[mf][jp * 2],     ph[mf][kc], &vl4[0]);
                    mma16(oacc[mf][jp * 2 + 1], ph[mf][kc], &vl4[2]);
                    mma16(oacc[mf][jp * 2],     pl[mf][kc], &vh4[0]);
                    mma16(oacc[mf][jp * 2 + 1], pl[mf][kc], &vh4[2]);
                }
            }
        }
        __syncthreads();
    }

    // -------- split-KV combine (once per CTA) via dead Q smem region --------
    float* exm = (float*)dsm;            // [2 kw][64 rows]
    float* exl = exm + 128;
    float* ob  = exl + 128;              // [64 rows][OBP]

    if (t == 0) {
#pragma unroll
        for (int mf = 0; mf < 2; mf++)
#pragma unroll
            for (int ab = 0; ab < 2; ab++) {
                const int r = wq0 + mf * 16 + g + ab * 8;
                exm[kw * 64 + r] = m_[mf][ab];
                exl[kw * 64 + r] = l_[mf][ab];
            }
    }
    __syncthreads();

    float sc_[2][2], linv[2][2];
#pragma unroll
    for (int mf = 0; mf < 2; mf++)
#pragma unroll
        for (int ab = 0; ab < 2; ab++) {
            const int r = wq0 + mf * 16 + g + ab * 8;
            const float mo = m_[mf][ab];
            const float mp = exm[(kw ^ 1) * 64 + r];
            const float lp = exl[(kw ^ 1) * 64 + r];
            const float mj = fmaxf(mo, mp);
            const float so = ex2(mo - mj), sp = ex2(mp - mj);
            sc_[mf][ab] = so;
            linv[mf][ab] = 1.f / (l_[mf][ab] * so + lp * sp);
        }

    if (kw == 0) {
#pragma unroll
        for (int mf = 0; mf < 2; mf++)
#pragma unroll
            for (int j = 0; j < 8; j++) {
                const int r0 = wq0 + mf * 16 + g, r1 = r0 + 8;
                const int col = j * 8 + t * 2;
                ob[r0 * OBP + col]     = oacc[mf][j][0] * sc_[mf][0];
                ob[r0 * OBP + col + 1] = oacc[mf][j][1] * sc_[mf][0];
                ob[r1 * OBP + col]     = oacc[mf][j][2] * sc_[mf][1];
                ob[r1 * OBP + col + 1] = oacc[mf][j][3] * sc_[mf][1];
            }
    }
    __syncthreads();
    if (kw == 1) {
#pragma unroll
        for (int mf = 0; mf < 2; mf++)
#pragma unroll
            for (int j = 0; j < 8; j++) {
                const int r0 = wq0 + mf * 16 + g, r1 = r0 + 8;
                const int col = j * 8 + t * 2;
                ob[r0 * OBP + col]     += oacc[mf][j][0] * sc_[mf][0];
                ob[r0 * OBP + col + 1] += oacc[mf][j][1] * sc_[mf][0];
                ob[r1 * OBP + col]     += oacc[mf][j][2] * sc_[mf][1];
                ob[r1 * OBP + col + 1] += oacc[mf][j][3] * sc_[mf][1];
            }
    }
    __syncthreads();

    // write merged-head pre-split output; each warp writes its kw half of cols
    const int b = bh >> 4, h = bh & 15;
#pragma unroll
    for (int mf = 0; mf < 2; mf++)
#pragma unroll
        for (int ab = 0; ab < 2; ab++) {
            const int r = wq0 + mf * 16 + g + ab * 8;
            const float li = linv[mf][ab];
            const int mo = (b * Ssz + q0 + r) * Esz + h * HDd;
#pragma unroll
            for (int j2 = 0; j2 < 4; j2++) {
                const int col = kw * 32 + j2 * 8 + t * 2;
                const float v0 = ob[r * OBP + col] * li;
                const float v1 = ob[r * OBP + col + 1] * li;
                uint32_t hi, lo;
                split2(v0, v1, hi, lo);
                *(uint32_t*)(sOh + mo + col) = hi;
                *(uint32_t*)(sOl + mo + col) = lo;
            }
        }
}

// ---------------------------------------------------------------------------
extern "C" void kernel_launch(void* const* d_in, const int* in_sizes, int n_in,
                              void* d_out, int out_size) {
    const float* x = (const float*)d_in[0];
    const float* w_qkv = (const float*)d_in[1];
    const float* b_qkv = (const float*)d_in[2];
    const float* w_proj = (const float*)d_in[3];
    const float* b_proj = (const float*)d_in[4];
    float* out = (float*)d_out;

    static bool attr_done = false;
    if (!attr_done) {
        cudaFuncSetAttribute(gemm_qkv, cudaFuncAttributeMaxDynamicSharedMemorySize, SMEM_DYN);
        cudaFuncSetAttribute(gemm_proj, cudaFuncAttributeMaxDynamicSharedMemorySize, SMEM_DYN);
        cudaFuncSetAttribute(attn_tc, cudaFuncAttributeMaxDynamicSharedMemorySize, AT_SMEM);
        attr_done = true;
    }

    split_plain<<<Msz * Esz / 4 / 256, 256>>>((const float4*)x);
    split_w_all<<<dim3(128, 32), 256>>>(w_qkv, w_proj);
    gemm_qkv<<<dim3(NQKV / 128, Msz / 128), 256, SMEM_DYN>>>(b_qkv);
    attn_tc<<<dim3(Ssz / 64, Bsz * Hsz), 128, AT_SMEM>>>();
    gemm_proj<<<dim3(Esz / 128, Msz / 128), 256, SMEM_DYN>>>(b_proj, out);
}